// round 11
// baseline (speedup 1.0000x reference)
#include <cuda_runtime.h>
#include <cstdint>

// Problem constants: B=2, T=2048, C=1024, H=16, D=64
#define TT 2048

// Scratch (allocation-free rule: __device__ globals)
__device__ float g_qkv[2 * 2048 * 3 * 1024];  // [B,T,3,H,D]
__device__ float g_y[2 * 2048 * 1024];        // [B,T,H,D]

__device__ __forceinline__ uint32_t f2tf32(float f) {
    uint32_t r;
    asm("cvt.rna.tf32.f32 %0, %1;" : "=r"(r) : "f"(f));
    return r;
}

__device__ __forceinline__ void mma_tf32(float* c, const uint32_t* a, const uint32_t* b) {
    asm volatile(
        "mma.sync.aligned.m16n8k8.row.col.f32.tf32.tf32.f32 "
        "{%0,%1,%2,%3}, {%4,%5,%6,%7}, {%8,%9}, {%0,%1,%2,%3};\n"
        : "+f"(c[0]), "+f"(c[1]), "+f"(c[2]), "+f"(c[3])
        : "r"(a[0]), "r"(a[1]), "r"(a[2]), "r"(a[3]), "r"(b[0]), "r"(b[1]));
}

// ---------------------------------------------------------------------------
// TF32 mma.sync GEMM, 64x64 warp tiles, fragment-order B staging.
// CTA: 128 threads, 4 warps (wm=warp>>1, wn=warp&1), tile 128x128, BK=16.
// A: classic [row][k] PADK=20 layout (STS.128 conflict-free, scalar frag LDS).
// B: frag-order 16B vectors, gather-staged, LDS.128 reads.
// ---------------------------------------------------------------------------
#define PADK 20

__global__ __launch_bounds__(128, 2)
void tf32_gemm_bias(const float* __restrict__ A, const float* __restrict__ Bw,
                    const float* __restrict__ bias, float* __restrict__ Cout,
                    int M, int N, int K) {
    __shared__ uint32_t As[2][128 * PADK];   // [row][k] padded
    __shared__ uint32_t Bf[2][2048];         // 512 frag vectors x 4

    const int tid = threadIdx.x;
    const int lane = tid & 31;
    const int warp = tid >> 5;          // 0..3 (also staging subgroup sg)
    const int gid = lane >> 2;          // 0..7
    const int tig = lane & 3;           // 0..3
    const int wm = warp >> 1;           // 0..1
    const int wn = warp & 1;            // 0..1
    const int br = blockIdx.y * 128;
    const int bc = blockIdx.x * 128;

    // A staging: thread owns row tid, 16 contiguous k per chunk
    const float* Ap = A + (long)(br + tid) * K;
    // B staging: thread owns frag vecs t=warp, (ks,wn') all 4 combos, lane=(gid,tig)
    const float* Bp = Bw + (long)tig * N + bc + warp * 16 + gid;

    float c[4][8][4];
#pragma unroll
    for (int mi = 0; mi < 4; mi++)
#pragma unroll
        for (int nj = 0; nj < 8; nj++)
#pragma unroll
            for (int e = 0; e < 4; e++) c[mi][nj][e] = 0.f;

    float4 av[4];          // A prefetch: 16 floats (one row-chunk)
    float bv[16];          // B prefetch: 16 gathered values

    // ---- load chunk 0 ----
#pragma unroll
    for (int j = 0; j < 4; j++) av[j] = *(const float4*)(Ap + j * 4);
#pragma unroll
    for (int ks = 0; ks < 2; ks++)
#pragma unroll
        for (int wni = 0; wni < 2; wni++)
#pragma unroll
            for (int e = 0; e < 4; e++) {   // e = u*2 + hi? order: (u,hi)=(0,0),(0,1),(1,0),(1,1)
                int u = e >> 1, hi = e & 1;
                bv[(ks * 2 + wni) * 4 + e] =
                    Bp[(long)(ks * 8 + hi * 4) * N + wni * 64 + u * 8];
            }
    // ---- store chunk 0 to stage 0 ----
    {
#pragma unroll
        for (int j = 0; j < 4; j++) {
            uint4 u;
            u.x = f2tf32(av[j].x); u.y = f2tf32(av[j].y);
            u.z = f2tf32(av[j].z); u.w = f2tf32(av[j].w);
            *(uint4*)&As[0][tid * PADK + j * 4] = u;
        }
#pragma unroll
        for (int ks = 0; ks < 2; ks++)
#pragma unroll
            for (int wni = 0; wni < 2; wni++) {
                const float* s = &bv[(ks * 2 + wni) * 4];
                uint4 u;
                u.x = f2tf32(s[0]);  // (u=0,hi=0) -> b[2t][0]
                u.y = f2tf32(s[1]);  // (u=0,hi=1) -> b[2t][1]
                u.z = f2tf32(s[2]);  // (u=1,hi=0) -> b[2t+1][0]
                u.w = f2tf32(s[3]);  // (u=1,hi=1) -> b[2t+1][1]
                int gb = ks * 8 + wni * 4 + warp;
                *(uint4*)&Bf[0][(gb * 32 + lane) * 4] = u;
            }
    }
    __syncthreads();

    int st = 0;
    const int nch = K >> 4;
    for (int ch = 0; ch < nch; ch++) {
        const bool hasNext = (ch + 1 < nch);
        if (hasNext) {
            const float* Ap2 = Ap + (ch + 1) * 16;
            const float* Bp2 = Bp + (long)(ch + 1) * 16 * N;
#pragma unroll
            for (int j = 0; j < 4; j++) av[j] = *(const float4*)(Ap2 + j * 4);
#pragma unroll
            for (int ks = 0; ks < 2; ks++)
#pragma unroll
                for (int wni = 0; wni < 2; wni++)
#pragma unroll
                    for (int e = 0; e < 4; e++) {
                        int u = e >> 1, hi = e & 1;
                        bv[(ks * 2 + wni) * 4 + e] =
                            Bp2[(long)(ks * 8 + hi * 4) * N + wni * 64 + u * 8];
                    }
        }

        // ---- math on stage st: 2 ks-steps of 32 mma ----
#pragma unroll
        for (int ks = 0; ks < 2; ks++) {
            uint32_t a[4][4];
#pragma unroll
            for (int mi = 0; mi < 4; mi++) {
                int base = (wm * 64 + mi * 16 + gid) * PADK + ks * 8 + tig;
                a[mi][0] = As[st][base];
                a[mi][1] = As[st][base + 8 * PADK];
                a[mi][2] = As[st][base + 4];
                a[mi][3] = As[st][base + 8 * PADK + 4];
            }
            uint4 b4[4];
#pragma unroll
            for (int t = 0; t < 4; t++)
                b4[t] = *(const uint4*)&Bf[st][((ks * 8 + wn * 4 + t) * 32 + lane) * 4];
#pragma unroll
            for (int mi = 0; mi < 4; mi++)
#pragma unroll
                for (int t = 0; t < 4; t++) {
                    uint32_t b0[2] = {b4[t].x, b4[t].y};
                    uint32_t b1[2] = {b4[t].z, b4[t].w};
                    mma_tf32(c[mi][2 * t],     a[mi], b0);
                    mma_tf32(c[mi][2 * t + 1], a[mi], b1);
                }
        }

        // ---- store prefetched chunk to the other stage ----
        if (hasNext) {
#pragma unroll
            for (int j = 0; j < 4; j++) {
                uint4 u;
                u.x = f2tf32(av[j].x); u.y = f2tf32(av[j].y);
                u.z = f2tf32(av[j].z); u.w = f2tf32(av[j].w);
                *(uint4*)&As[st ^ 1][tid * PADK + j * 4] = u;
            }
#pragma unroll
            for (int ks = 0; ks < 2; ks++)
#pragma unroll
                for (int wni = 0; wni < 2; wni++) {
                    const float* s = &bv[(ks * 2 + wni) * 4];
                    uint4 u;
                    u.x = f2tf32(s[0]); u.y = f2tf32(s[1]);
                    u.z = f2tf32(s[2]); u.w = f2tf32(s[3]);
                    int gb = ks * 8 + wni * 4 + warp;
                    *(uint4*)&Bf[st ^ 1][(gb * 32 + lane) * 4] = u;
                }
        }
        __syncthreads();
        st ^= 1;
    }

    // ---- epilogue: bias + store ----
#pragma unroll
    for (int mi = 0; mi < 4; mi++) {
        int row = br + wm * 64 + mi * 16 + gid;
#pragma unroll
        for (int nj = 0; nj < 8; nj++) {
            int col = bc + wn * 64 + nj * 8 + tig * 2;
            float2 bb = *(const float2*)(bias + col);
            *(float2*)(Cout + (long)row * N + col) =
                make_float2(c[mi][nj][0] + bb.x, c[mi][nj][1] + bb.y);
            *(float2*)(Cout + (long)(row + 8) * N + col) =
                make_float2(c[mi][nj][2] + bb.x, c[mi][nj][3] + bb.y);
        }
    }
}

// ---------------------------------------------------------------------------
// Fused per-head RMSNorm + RoPE on q and k slots of g_qkv (in place).
// ---------------------------------------------------------------------------
__global__ __launch_bounds__(256)
void norm_rope_kernel(float* __restrict__ qkv,
                      const float* __restrict__ cosb,
                      const float* __restrict__ sinb) {
    __shared__ float qn[1024];
    __shared__ float kn[1024];
    const int bt = blockIdx.x;
    const int t = bt & (TT - 1);
    const int tid = threadIdx.x;
    float* qrow = qkv + (long)bt * 3072;
    float* krow = qrow + 1024;

    float4 qv = *(const float4*)(qrow + tid * 4);
    float4 kv = *(const float4*)(krow + tid * 4);
    float qs = qv.x * qv.x + qv.y * qv.y + qv.z * qv.z + qv.w * qv.w;
    float ks = kv.x * kv.x + kv.y * kv.y + kv.z * kv.z + kv.w * kv.w;
#pragma unroll
    for (int o = 8; o > 0; o >>= 1) {
        qs += __shfl_xor_sync(0xffffffffu, qs, o);
        ks += __shfl_xor_sync(0xffffffffu, ks, o);
    }
    const float qsc = rsqrtf(qs * (1.f / 64.f) + 1.1920929e-07f);
    const float ksc = rsqrtf(ks * (1.f / 64.f) + 1.1920929e-07f);
    float4 qn4 = make_float4(qv.x * qsc, qv.y * qsc, qv.z * qsc, qv.w * qsc);
    float4 kn4 = make_float4(kv.x * ksc, kv.y * ksc, kv.z * ksc, kv.w * ksc);
    *(float4*)&qn[tid * 4] = qn4;
    *(float4*)&kn[tid * 4] = kn4;
    __syncthreads();

    const int i = tid * 4;
    const int d = i & 63;
    const int base = i - d;
    float4 cv = *(const float4*)(cosb + t * 64 + d);
    float4 sv = *(const float4*)(sinb + t * 64 + d);
    float4 rq, rk;
    if (d < 32) {
        float4 pq = *(const float4*)&qn[base + d + 32];
        float4 pk = *(const float4*)&kn[base + d + 32];
        rq = make_float4(-pq.x, -pq.y, -pq.z, -pq.w);
        rk = make_float4(-pk.x, -pk.y, -pk.z, -pk.w);
    } else {
        rq = *(const float4*)&qn[base + d - 32];
        rk = *(const float4*)&kn[base + d - 32];
    }
    float4 oq, ok;
    oq.x = qn4.x * cv.x + rq.x * sv.x;  oq.y = qn4.y * cv.y + rq.y * sv.y;
    oq.z = qn4.z * cv.z + rq.z * sv.z;  oq.w = qn4.w * cv.w + rq.w * sv.w;
    ok.x = kn4.x * cv.x + rk.x * sv.x;  ok.y = kn4.y * cv.y + rk.y * sv.y;
    ok.z = kn4.z * cv.z + rk.z * sv.z;  ok.w = kn4.w * cv.w + rk.w * sv.w;
    *(float4*)(qrow + i) = oq;
    *(float4*)(krow + i) = ok;
}

// ---------------------------------------------------------------------------
// TF32 flash attention with fixed-max softmax (round-9 best, unchanged).
// ---------------------------------------------------------------------------
#define KPAD 68
#define VPAD 72
#define PPAD 68
#define ATT_SMEM ((64 * KPAD + 64 * VPAD + 128 * PPAD) * 4)

__global__ __launch_bounds__(256, 2)
void attn_tf32_kernel(const float* __restrict__ qkv, float* __restrict__ y) {
    extern __shared__ uint32_t smu[];
    uint32_t* Ks = smu;
    uint32_t* Vs = Ks + 64 * KPAD;
    uint32_t* Ps = Vs + 64 * VPAD;

    const int qb = (int)(gridDim.x - 1) - (int)blockIdx.x;
    const int h = blockIdx.y, b = blockIdx.z;
    const int tid = threadIdx.x;
    const int lane = tid & 31, warp = tid >> 5;
    const int gid = lane >> 2, tig = lane & 3;
    const int r0 = warp * 16;

    {
        const int row = tid >> 1;
        const int dh = (tid & 1) * 32;
        const float* src = qkv + ((long)(b * TT + qb * 128 + row) * 3) * 1024 + h * 64 + dh;
#pragma unroll
        for (int j = 0; j < 8; j++) {
            float4 v = *(const float4*)(src + j * 4);
            uint4 s;
            s.x = f2tf32(v.x * 0.125f); s.y = f2tf32(v.y * 0.125f);
            s.z = f2tf32(v.z * 0.125f); s.w = f2tf32(v.w * 0.125f);
            *(uint4*)&Ps[row * PPAD + dh + j * 4] = s;
        }
    }
    __syncthreads();
    uint32_t qa[8][4];
#pragma unroll
    for (int ks = 0; ks < 8; ks++) {
        int base = (r0 + gid) * PPAD + ks * 8 + tig;
        qa[ks][0] = Ps[base];
        qa[ks][1] = Ps[base + 8 * PPAD];
        qa[ks][2] = Ps[base + 4];
        qa[ks][3] = Ps[base + 8 * PPAD + 4];
    }

    float cO[8][4];
#pragma unroll
    for (int nj = 0; nj < 8; nj++)
#pragma unroll
        for (int e = 0; e < 4; e++) cO[nj][e] = 0.f;
    float lp0 = 0.f, lp1 = 0.f;

    const int nkv = 2 * (qb + 1);
    for (int kb = 0; kb < nkv; kb++) {
        __syncthreads();
        {
            const int row = tid >> 2;
            const int dh = (tid & 3) * 16;
            const float* ksrc = qkv + ((long)(b * TT + kb * 64 + row) * 3 + 1) * 1024 + h * 64 + dh;
            const float* vsrc = qkv + ((long)(b * TT + kb * 64 + row) * 3 + 2) * 1024 + h * 64 + dh;
#pragma unroll
            for (int j = 0; j < 4; j++) {
                float4 v = *(const float4*)(ksrc + j * 4);
                uint4 s;
                s.x = f2tf32(v.x); s.y = f2tf32(v.y); s.z = f2tf32(v.z); s.w = f2tf32(v.w);
                *(uint4*)&Ks[row * KPAD + dh + j * 4] = s;
                v = *(const float4*)(vsrc + j * 4);
                s.x = f2tf32(v.x); s.y = f2tf32(v.y); s.z = f2tf32(v.z); s.w = f2tf32(v.w);
                *(uint4*)&Vs[row * VPAD + dh + j * 4] = s;
            }
        }
        __syncthreads();

        float cS[8][4];
#pragma unroll
        for (int nj = 0; nj < 8; nj++)
#pragma unroll
            for (int e = 0; e < 4; e++) cS[nj][e] = 0.f;

#pragma unroll
        for (int ks = 0; ks < 8; ks++) {
#pragma unroll
            for (int nj = 0; nj < 8; nj++) {
                uint32_t bb[2];
                int base = (nj * 8 + gid) * KPAD + ks * 8 + tig;
                bb[0] = Ks[base];
                bb[1] = Ks[base + 4];
                mma_tf32(cS[nj], qa[ks], bb);
            }
        }

        if (kb >= 2 * qb) {
            int rA = qb * 128 + r0 + gid;
            int rB = rA + 8;
#pragma unroll
            for (int nj = 0; nj < 8; nj++) {
                int col = kb * 64 + nj * 8 + 2 * tig;
                if (col     > rA) cS[nj][0] = -3.0e38f;
                if (col + 1 > rA) cS[nj][1] = -3.0e38f;
                if (col     > rB) cS[nj][2] = -3.0e38f;
                if (col + 1 > rB) cS[nj][3] = -3.0e38f;
            }
        }

#pragma unroll
        for (int nj = 0; nj < 8; nj++) {
            cS[nj][0] = __expf(cS[nj][0] - 8.0f); lp0 += cS[nj][0];
            cS[nj][1] = __expf(cS[nj][1] - 8.0f); lp0 += cS[nj][1];
            cS[nj][2] = __expf(cS[nj][2] - 8.0f); lp1 += cS[nj][2];
            cS[nj][3] = __expf(cS[nj][3] - 8.0f); lp1 += cS[nj][3];
        }

#pragma unroll
        for (int nj = 0; nj < 8; nj++) {
            int col = nj * 8 + 2 * tig;
            uint2 p0 = make_uint2(f2tf32(cS[nj][0]), f2tf32(cS[nj][1]));
            *(uint2*)&Ps[(r0 + gid) * PPAD + col] = p0;
            uint2 p1 = make_uint2(f2tf32(cS[nj][2]), f2tf32(cS[nj][3]));
            *(uint2*)&Ps[(r0 + gid + 8) * PPAD + col] = p1;
        }
        __syncwarp();

#pragma unroll
        for (int ks = 0; ks < 8; ks++) {
            uint32_t pa[4];
            int abase = (r0 + gid) * PPAD + ks * 8 + tig;
            pa[0] = Ps[abase];
            pa[1] = Ps[abase + 8 * PPAD];
            pa[2] = Ps[abase + 4];
            pa[3] = Ps[abase + 8 * PPAD + 4];
#pragma unroll
            for (int nj = 0; nj < 8; nj++) {
                uint32_t bb[2];
                int bbase = (ks * 8 + tig) * VPAD + nj * 8 + gid;
                bb[0] = Vs[bbase];
                bb[1] = Vs[bbase + 4 * VPAD];
                mma_tf32(cO[nj], pa, bb);
            }
        }
    }

    lp0 += __shfl_xor_sync(0xffffffffu, lp0, 1);
    lp0 += __shfl_xor_sync(0xffffffffu, lp0, 2);
    lp1 += __shfl_xor_sync(0xffffffffu, lp1, 1);
    lp1 += __shfl_xor_sync(0xffffffffu, lp1, 2);
    float inv0 = 1.0f / lp0, inv1 = 1.0f / lp1;
    long rowA = (long)(b * TT + qb * 128 + r0 + gid) * 1024 + h * 64;
    long rowB = rowA + 8 * 1024;
#pragma unroll
    for (int nj = 0; nj < 8; nj++) {
        int col = nj * 8 + 2 * tig;
        *(float2*)(y + rowA + col) = make_float2(cO[nj][0] * inv0, cO[nj][1] * inv0);
        *(float2*)(y + rowB + col) = make_float2(cO[nj][2] * inv1, cO[nj][3] * inv1);
    }
}

// ---------------------------------------------------------------------------
extern "C" void kernel_launch(void* const* d_in, const int* in_sizes, int n_in,
                              void* d_out, int out_size) {
    const float* x      = (const float*)d_in[0];
    const float* cosb   = (const float*)d_in[1];
    const float* sinb   = (const float*)d_in[2];
    const float* W_attn = (const float*)d_in[3];
    const float* b_attn = (const float*)d_in[4];
    const float* W_proj = (const float*)d_in[5];
    const float* b_proj = (const float*)d_in[6];
    float* out = (float*)d_out;

    float *qkv, *y;
    cudaGetSymbolAddress((void**)&qkv, g_qkv);
    cudaGetSymbolAddress((void**)&y, g_y);

    // 1) QKV GEMM (TF32, 64x64 warp tiles): [4096,1024] @ [1024,3072] + bias
    tf32_gemm_bias<<<dim3(3072 / 128, 4096 / 128), 128>>>(x, W_attn, b_attn, qkv, 4096, 3072, 1024);

    // 2) per-head RMSNorm + RoPE on q,k (in place)
    norm_rope_kernel<<<2 * TT, 256>>>(qkv, cosb, sinb);

    // 3) causal flash attention (TF32, fixed-max softmax)
    cudaFuncSetAttribute(attn_tf32_kernel, cudaFuncAttributeMaxDynamicSharedMemorySize, ATT_SMEM);
    attn_tf32_kernel<<<dim3(TT / 128, 16, 2), 256, ATT_SMEM>>>(qkv, y);

    // 4) output projection (TF32, 64x64 warp tiles): [4096,1024] @ [1024,1024] + bias
    tf32_gemm_bias<<<dim3(1024 / 128, 4096 / 128), 128>>>(y, W_proj, b_proj, out, 4096, 1024, 1024);
}

// round 12
// speedup vs baseline: 1.5014x; 1.5014x over previous
#include <cuda_runtime.h>
#include <cuda_fp16.h>
#include <cstdint>

// Problem constants: B=2, T=2048, C=1024, H=16, D=64
#define TT 2048

// Scratch (allocation-free rule: __device__ globals)
__device__ float g_qkv[2 * 2048 * 3 * 1024];   // [B,T,3,H,D]
__device__ float g_y[2 * 2048 * 1024];         // [B,T,H,D]
__device__ __half g_wta16[3072 * 1024];        // W_attn^T fp16 [N][K]
__device__ __half g_wtp16[1024 * 1024];        // W_proj^T fp16 [N][K]

__device__ __forceinline__ uint32_t f2h2(float lo, float hi) {
    __half2 h = __floats2half2_rn(lo, hi);   // x = lo (low half)
    return *reinterpret_cast<uint32_t*>(&h);
}

__device__ __forceinline__ void mma_f16(float* c, const uint32_t* a, const uint32_t* b) {
    asm volatile(
        "mma.sync.aligned.m16n8k16.row.col.f32.f16.f16.f32 "
        "{%0,%1,%2,%3}, {%4,%5,%6,%7}, {%8,%9}, {%0,%1,%2,%3};\n"
        : "+f"(c[0]), "+f"(c[1]), "+f"(c[2]), "+f"(c[3])
        : "r"(a[0]), "r"(a[1]), "r"(a[2]), "r"(a[3]), "r"(b[0]), "r"(b[1]));
}

// ---------------------------------------------------------------------------
// Weight transpose + fp16 convert: Wt16[n][k] = (half)W[k][n]
// ---------------------------------------------------------------------------
__global__ __launch_bounds__(256)
void transpose_w_h(const float* __restrict__ W, __half* __restrict__ Wt, int K, int N) {
    __shared__ float t[32][33];
    const int n0 = blockIdx.x * 32, k0 = blockIdx.y * 32;
    const int x = threadIdx.x & 31, y = threadIdx.x >> 5;
#pragma unroll
    for (int i = 0; i < 4; i++)
        t[y + 8 * i][x] = W[(long)(k0 + y + 8 * i) * N + n0 + x];
    __syncthreads();
#pragma unroll
    for (int i = 0; i < 4; i++)
        Wt[(long)(n0 + y + 8 * i) * K + k0 + x] = __float2half_rn(t[x][y + 8 * i]);
}

// ---------------------------------------------------------------------------
// FP16 mma.sync GEMM with bias: C[M,N] = A[M,K] @ Bt16[N,K]^T + bias[N]
// 256 thr, 8 warps (4x2), 128x128 tile, BK=32, 2-stage double buffer.
// As/Bs: 40-half rows (20-word pitch): frag words gid*20+tig -> all 32 banks.
// ---------------------------------------------------------------------------
#define AP 20   // word pitch (40 halves per row: 32 data + 8 pad)

__global__ __launch_bounds__(256, 2)
void h16_gemm_bias(const float* __restrict__ A, const __half* __restrict__ Bt,
                   const float* __restrict__ bias, float* __restrict__ Cout,
                   int M, int N, int K) {
    __shared__ uint32_t As[2][128 * AP];
    __shared__ uint32_t Bs[2][128 * AP];

    const int tid = threadIdx.x;
    const int lane = tid & 31;
    const int warp = tid >> 5;
    const int gid = lane >> 2;
    const int tig = lane & 3;
    const int wm = warp >> 1;       // 0..3
    const int wn = warp & 1;        // 0..1
    const int m0w = wm * 32;
    const int n0w = wn * 64;
    const int br = blockIdx.y * 128;
    const int bc = blockIdx.x * 128;

    const int srow = tid >> 1;            // staging row (A-row / B-n)
    const int sh   = (tid & 1);           // which 16-half chunk

    const float* Ap = A + (long)(br + srow) * K + sh * 16;
    const __half* Bp = Bt + (long)(bc + srow) * K + sh * 16;

    float c[2][8][4];
#pragma unroll
    for (int mi = 0; mi < 2; mi++)
#pragma unroll
        for (int nj = 0; nj < 8; nj++)
#pragma unroll
            for (int e = 0; e < 4; e++) c[mi][nj][e] = 0.f;

    float4 av[4];
    uint4 bv0, bv1;

    // ---- prologue: load + store chunk 0 ----
#pragma unroll
    for (int j = 0; j < 4; j++) av[j] = *(const float4*)(Ap + j * 4);
    bv0 = ((const uint4*)Bp)[0];
    bv1 = ((const uint4*)Bp)[1];
    {
        uint4 u;
        u.x = f2h2(av[0].x, av[0].y); u.y = f2h2(av[0].z, av[0].w);
        u.z = f2h2(av[1].x, av[1].y); u.w = f2h2(av[1].z, av[1].w);
        *(uint4*)&As[0][srow * AP + sh * 8] = u;
        u.x = f2h2(av[2].x, av[2].y); u.y = f2h2(av[2].z, av[2].w);
        u.z = f2h2(av[3].x, av[3].y); u.w = f2h2(av[3].z, av[3].w);
        *(uint4*)&As[0][srow * AP + sh * 8 + 4] = u;
        *(uint4*)&Bs[0][srow * AP + sh * 8] = bv0;
        *(uint4*)&Bs[0][srow * AP + sh * 8 + 4] = bv1;
    }
    __syncthreads();

    int st = 0;
    const int nch = K >> 5;   // BK = 32
    for (int ch = 0; ch < nch; ch++) {
        const bool hasNext = (ch + 1 < nch);
        if (hasNext) {
            const float* Ap2 = Ap + (ch + 1) * 32;
            const __half* Bp2 = Bp + (ch + 1) * 32;
#pragma unroll
            for (int j = 0; j < 4; j++) av[j] = *(const float4*)(Ap2 + j * 4);
            bv0 = ((const uint4*)Bp2)[0];
            bv1 = ((const uint4*)Bp2)[1];
        }

        // ---- math: 2 k16-steps ----
#pragma unroll
        for (int ks = 0; ks < 2; ks++) {
            uint32_t a[2][4];
#pragma unroll
            for (int mi = 0; mi < 2; mi++) {
                int base = (m0w + mi * 16 + gid) * AP + ks * 8 + tig;
                a[mi][0] = As[st][base];
                a[mi][1] = As[st][base + 8 * AP];
                a[mi][2] = As[st][base + 4];
                a[mi][3] = As[st][base + 8 * AP + 4];
            }
#pragma unroll
            for (int nj = 0; nj < 8; nj++) {
                uint32_t b[2];
                int base = (n0w + nj * 8 + gid) * AP + ks * 8 + tig;
                b[0] = Bs[st][base];
                b[1] = Bs[st][base + 4];
                mma_f16(c[0][nj], a[0], b);
                mma_f16(c[1][nj], a[1], b);
            }
        }

        // ---- store prefetched chunk ----
        if (hasNext) {
            uint4 u;
            u.x = f2h2(av[0].x, av[0].y); u.y = f2h2(av[0].z, av[0].w);
            u.z = f2h2(av[1].x, av[1].y); u.w = f2h2(av[1].z, av[1].w);
            *(uint4*)&As[st ^ 1][srow * AP + sh * 8] = u;
            u.x = f2h2(av[2].x, av[2].y); u.y = f2h2(av[2].z, av[2].w);
            u.z = f2h2(av[3].x, av[3].y); u.w = f2h2(av[3].z, av[3].w);
            *(uint4*)&As[st ^ 1][srow * AP + sh * 8 + 4] = u;
            *(uint4*)&Bs[st ^ 1][srow * AP + sh * 8] = bv0;
            *(uint4*)&Bs[st ^ 1][srow * AP + sh * 8 + 4] = bv1;
        }
        __syncthreads();
        st ^= 1;
    }

    // ---- epilogue: bias + store ----
#pragma unroll
    for (int mi = 0; mi < 2; mi++) {
        int row = br + m0w + mi * 16 + gid;
#pragma unroll
        for (int nj = 0; nj < 8; nj++) {
            int col = bc + n0w + nj * 8 + tig * 2;
            float2 bb = *(const float2*)(bias + col);
            *(float2*)(Cout + (long)row * N + col) =
                make_float2(c[mi][nj][0] + bb.x, c[mi][nj][1] + bb.y);
            *(float2*)(Cout + (long)(row + 8) * N + col) =
                make_float2(c[mi][nj][2] + bb.x, c[mi][nj][3] + bb.y);
        }
    }
}

// ---------------------------------------------------------------------------
// Fused per-head RMSNorm + RoPE on q and k slots of g_qkv (in place).
// ---------------------------------------------------------------------------
__global__ __launch_bounds__(256)
void norm_rope_kernel(float* __restrict__ qkv,
                      const float* __restrict__ cosb,
                      const float* __restrict__ sinb) {
    __shared__ float qn[1024];
    __shared__ float kn[1024];
    const int bt = blockIdx.x;
    const int t = bt & (TT - 1);
    const int tid = threadIdx.x;
    float* qrow = qkv + (long)bt * 3072;
    float* krow = qrow + 1024;

    float4 qv = *(const float4*)(qrow + tid * 4);
    float4 kv = *(const float4*)(krow + tid * 4);
    float qs = qv.x * qv.x + qv.y * qv.y + qv.z * qv.z + qv.w * qv.w;
    float ks = kv.x * kv.x + kv.y * kv.y + kv.z * kv.z + kv.w * kv.w;
#pragma unroll
    for (int o = 8; o > 0; o >>= 1) {
        qs += __shfl_xor_sync(0xffffffffu, qs, o);
        ks += __shfl_xor_sync(0xffffffffu, ks, o);
    }
    const float qsc = rsqrtf(qs * (1.f / 64.f) + 1.1920929e-07f);
    const float ksc = rsqrtf(ks * (1.f / 64.f) + 1.1920929e-07f);
    float4 qn4 = make_float4(qv.x * qsc, qv.y * qsc, qv.z * qsc, qv.w * qsc);
    float4 kn4 = make_float4(kv.x * ksc, kv.y * ksc, kv.z * ksc, kv.w * ksc);
    *(float4*)&qn[tid * 4] = qn4;
    *(float4*)&kn[tid * 4] = kn4;
    __syncthreads();

    const int i = tid * 4;
    const int d = i & 63;
    const int base = i - d;
    float4 cv = *(const float4*)(cosb + t * 64 + d);
    float4 sv = *(const float4*)(sinb + t * 64 + d);
    float4 rq, rk;
    if (d < 32) {
        float4 pq = *(const float4*)&qn[base + d + 32];
        float4 pk = *(const float4*)&kn[base + d + 32];
        rq = make_float4(-pq.x, -pq.y, -pq.z, -pq.w);
        rk = make_float4(-pk.x, -pk.y, -pk.z, -pk.w);
    } else {
        rq = *(const float4*)&qn[base + d - 32];
        rk = *(const float4*)&kn[base + d - 32];
    }
    float4 oq, ok;
    oq.x = qn4.x * cv.x + rq.x * sv.x;  oq.y = qn4.y * cv.y + rq.y * sv.y;
    oq.z = qn4.z * cv.z + rq.z * sv.z;  oq.w = qn4.w * cv.w + rq.w * sv.w;
    ok.x = kn4.x * cv.x + rk.x * sv.x;  ok.y = kn4.y * cv.y + rk.y * sv.y;
    ok.z = kn4.z * cv.z + rk.z * sv.z;  ok.w = kn4.w * cv.w + rk.w * sv.w;
    *(float4*)(qrow + i) = oq;
    *(float4*)(krow + i) = ok;
}

// ---------------------------------------------------------------------------
// FP16 flash attention, fixed-max softmax (|s|<=8 after rms_norm + 1/8 scale).
// 256 thr, 8 warps x 16 rows, BKV=64. K/Q/P at 36-word pitch (conflict-free
// frag LDS); V natural [col][d], B-frags via ldmatrix.x2.trans.
// ---------------------------------------------------------------------------
#define TPW 36   // word pitch = 72 halves (64 data + 8 pad)
#define ATT_SMEM ((64 * TPW + 64 * TPW + 128 * TPW) * 4)

__global__ __launch_bounds__(256, 2)
void attn_h16_kernel(const float* __restrict__ qkv, float* __restrict__ y) {
    extern __shared__ uint32_t smu[];
    uint32_t* Ks = smu;                   // [64][TPW]  (col-major rows: [token][d])
    uint32_t* Vs = Ks + 64 * TPW;         // [64][TPW]  ([token][d], natural)
    uint32_t* Ps = Vs + 64 * TPW;         // [128][TPW] (P + Q staging)

    const int qb = (int)(gridDim.x - 1) - (int)blockIdx.x;  // heavy CTAs first
    const int h = blockIdx.y, b = blockIdx.z;
    const int tid = threadIdx.x;
    const int lane = tid & 31, warp = tid >> 5;
    const int gid = lane >> 2, tig = lane & 3;
    const int r0 = warp * 16;
    const uint32_t vs_u32 = (uint32_t)__cvta_generic_to_shared(Vs);

    // ---- Stage Q (scaled, fp16) into Ps; load A-fragments ----
    {
        const int row = tid >> 1;
        const int dh = (tid & 1) * 32;   // halves offset
        const float* src = qkv + ((long)(b * TT + qb * 128 + row) * 3) * 1024 + h * 64 + dh;
#pragma unroll
        for (int j = 0; j < 8; j++) {
            float4 v = *(const float4*)(src + j * 4);
            uint2 u;
            u.x = f2h2(v.x * 0.125f, v.y * 0.125f);
            u.y = f2h2(v.z * 0.125f, v.w * 0.125f);
            *(uint2*)&Ps[row * TPW + (tid & 1) * 16 + j * 2] = u;
        }
    }
    __syncthreads();
    uint32_t qa[4][4];
#pragma unroll
    for (int ks = 0; ks < 4; ks++) {
        int base = (r0 + gid) * TPW + ks * 8 + tig;
        qa[ks][0] = Ps[base];
        qa[ks][1] = Ps[base + 8 * TPW];
        qa[ks][2] = Ps[base + 4];
        qa[ks][3] = Ps[base + 8 * TPW + 4];
    }

    float cO[8][4];
#pragma unroll
    for (int nj = 0; nj < 8; nj++)
#pragma unroll
        for (int e = 0; e < 4; e++) cO[nj][e] = 0.f;
    float lp0 = 0.f, lp1 = 0.f;

    const int nkv = 2 * (qb + 1);
    for (int kb = 0; kb < nkv; kb++) {
        __syncthreads();  // prev-iter readers done with Ks/Vs/Ps
        // ---- Stage K, V tiles (64 tokens x 64 d, fp16) ----
        {
            const int row = tid >> 2;
            const int dh = (tid & 3) * 16;
            const float* ksrc = qkv + ((long)(b * TT + kb * 64 + row) * 3 + 1) * 1024 + h * 64 + dh;
            const float* vsrc = qkv + ((long)(b * TT + kb * 64 + row) * 3 + 2) * 1024 + h * 64 + dh;
#pragma unroll
            for (int j = 0; j < 2; j++) {
                float4 v0 = *(const float4*)(ksrc + j * 8);
                float4 v1 = *(const float4*)(ksrc + j * 8 + 4);
                uint4 u;
                u.x = f2h2(v0.x, v0.y); u.y = f2h2(v0.z, v0.w);
                u.z = f2h2(v1.x, v1.y); u.w = f2h2(v1.z, v1.w);
                *(uint4*)&Ks[row * TPW + (tid & 3) * 8 + j * 4] = u;
                v0 = *(const float4*)(vsrc + j * 8);
                v1 = *(const float4*)(vsrc + j * 8 + 4);
                u.x = f2h2(v0.x, v0.y); u.y = f2h2(v0.z, v0.w);
                u.z = f2h2(v1.x, v1.y); u.w = f2h2(v1.z, v1.w);
                *(uint4*)&Vs[row * TPW + (tid & 3) * 8 + j * 4] = u;
            }
        }
        __syncthreads();

        // ---- S = Q @ K^T : 4 k16-steps x 8 n-tiles ----
        float cS[8][4];
#pragma unroll
        for (int nj = 0; nj < 8; nj++)
#pragma unroll
            for (int e = 0; e < 4; e++) cS[nj][e] = 0.f;

#pragma unroll
        for (int ks = 0; ks < 4; ks++) {
#pragma unroll
            for (int nj = 0; nj < 8; nj++) {
                uint32_t bb[2];
                int base = (nj * 8 + gid) * TPW + ks * 8 + tig;
                bb[0] = Ks[base];
                bb[1] = Ks[base + 4];
                mma_f16(cS[nj], qa[ks], bb);
            }
        }

        if (kb >= 2 * qb) {  // tiles intersecting the causal diagonal
            int rA = qb * 128 + r0 + gid;
            int rB = rA + 8;
#pragma unroll
            for (int nj = 0; nj < 8; nj++) {
                int col = kb * 64 + nj * 8 + 2 * tig;
                if (col     > rA) cS[nj][0] = -3.0e38f;
                if (col + 1 > rA) cS[nj][1] = -3.0e38f;
                if (col     > rB) cS[nj][2] = -3.0e38f;
                if (col + 1 > rB) cS[nj][3] = -3.0e38f;
            }
        }

        // ---- Fixed-max softmax: p = exp(s - 8) ----
#pragma unroll
        for (int nj = 0; nj < 8; nj++) {
            cS[nj][0] = __expf(cS[nj][0] - 8.0f); lp0 += cS[nj][0];
            cS[nj][1] = __expf(cS[nj][1] - 8.0f); lp0 += cS[nj][1];
            cS[nj][2] = __expf(cS[nj][2] - 8.0f); lp1 += cS[nj][2];
            cS[nj][3] = __expf(cS[nj][3] - 8.0f); lp1 += cS[nj][3];
        }

        // ---- Store P (fp16); warp-private rows ----
#pragma unroll
        for (int nj = 0; nj < 8; nj++) {
            Ps[(r0 + gid) * TPW + nj * 4 + tig]     = f2h2(cS[nj][0], cS[nj][1]);
            Ps[(r0 + gid + 8) * TPW + nj * 4 + tig] = f2h2(cS[nj][2], cS[nj][3]);
        }
        __syncwarp();

        // ---- O += P @ V : 4 k16-steps; V frags via ldmatrix.x2.trans ----
#pragma unroll
        for (int ks = 0; ks < 4; ks++) {
            uint32_t pa[4];
            int abase = (r0 + gid) * TPW + ks * 8 + tig;
            pa[0] = Ps[abase];
            pa[1] = Ps[abase + 8 * TPW];
            pa[2] = Ps[abase + 4];
            pa[3] = Ps[abase + 8 * TPW + 4];
            const uint32_t vrow = vs_u32 + (uint32_t)((ks * 16 + (lane & 15)) * (TPW * 4));
#pragma unroll
            for (int nj = 0; nj < 8; nj++) {
                uint32_t bb0, bb1;
                asm volatile(
                    "ldmatrix.sync.aligned.m8n8.x2.trans.shared.b16 {%0,%1}, [%2];"
                    : "=r"(bb0), "=r"(bb1) : "r"(vrow + nj * 16));
                uint32_t bb[2] = {bb0, bb1};
                mma_f16(cO[nj], pa, bb);
            }
        }
    }

    // ---- Final row-sum reduction + epilogue ----
    lp0 += __shfl_xor_sync(0xffffffffu, lp0, 1);
    lp0 += __shfl_xor_sync(0xffffffffu, lp0, 2);
    lp1 += __shfl_xor_sync(0xffffffffu, lp1, 1);
    lp1 += __shfl_xor_sync(0xffffffffu, lp1, 2);
    float inv0 = 1.0f / lp0, inv1 = 1.0f / lp1;
    long rowA = (long)(b * TT + qb * 128 + r0 + gid) * 1024 + h * 64;
    long rowB = rowA + 8 * 1024;
#pragma unroll
    for (int nj = 0; nj < 8; nj++) {
        int col = nj * 8 + 2 * tig;
        *(float2*)(y + rowA + col) = make_float2(cO[nj][0] * inv0, cO[nj][1] * inv0);
        *(float2*)(y + rowB + col) = make_float2(cO[nj][2] * inv1, cO[nj][3] * inv1);
    }
}

// ---------------------------------------------------------------------------
extern "C" void kernel_launch(void* const* d_in, const int* in_sizes, int n_in,
                              void* d_out, int out_size) {
    const float* x      = (const float*)d_in[0];
    const float* cosb   = (const float*)d_in[1];
    const float* sinb   = (const float*)d_in[2];
    const float* W_attn = (const float*)d_in[3];
    const float* b_attn = (const float*)d_in[4];
    const float* W_proj = (const float*)d_in[5];
    const float* b_proj = (const float*)d_in[6];
    float* out = (float*)d_out;

    float *qkv, *y;
    __half *wta, *wtp;
    cudaGetSymbolAddress((void**)&qkv, g_qkv);
    cudaGetSymbolAddress((void**)&y, g_y);
    cudaGetSymbolAddress((void**)&wta, g_wta16);
    cudaGetSymbolAddress((void**)&wtp, g_wtp16);

    // 0) transpose + convert weights to fp16 [N][K]
    transpose_w_h<<<dim3(96, 32), 256>>>(W_attn, wta, 1024, 3072);
    transpose_w_h<<<dim3(32, 32), 256>>>(W_proj, wtp, 1024, 1024);

    // 1) QKV GEMM (fp16 m16n8k16): [4096,1024] @ [1024,3072] + bias
    h16_gemm_bias<<<dim3(3072 / 128, 4096 / 128), 256>>>(x, wta, b_attn, qkv, 4096, 3072, 1024);

    // 2) per-head RMSNorm + RoPE on q,k (in place)
    norm_rope_kernel<<<2 * TT, 256>>>(qkv, cosb, sinb);

    // 3) causal flash attention (fp16, fixed-max softmax)
    cudaFuncSetAttribute(attn_h16_kernel, cudaFuncAttributeMaxDynamicSharedMemorySize, ATT_SMEM);
    attn_h16_kernel<<<dim3(TT / 128, 16, 2), 256, ATT_SMEM>>>(qkv, y);

    // 4) output projection (fp16 m16n8k16): [4096,1024] @ [1024,1024] + bias
    h16_gemm_bias<<<dim3(1024 / 128, 4096 / 128), 256>>>(y, wtp, b_proj, out, 4096, 1024, 1024);
}

// round 13
// speedup vs baseline: 2.1662x; 1.4428x over previous
#include <cuda_runtime.h>
#include <cuda_fp16.h>
#include <cstdint>

// Problem constants: B=2, T=2048, C=1024, H=16, D=64
#define TT 2048

// Scratch (allocation-free rule: __device__ globals)
__device__ __half g_x16[2 * 2048 * 1024];        // x fp16
__device__ __half g_qkv16[2 * 2048 * 3 * 1024];  // [B,T,3,H,D] fp16
__device__ __half g_y16[2 * 2048 * 1024];        // [B,T,H,D] fp16
__device__ __half g_wta16[3072 * 1024];          // W_attn^T fp16 [N][K]
__device__ __half g_wtp16[1024 * 1024];          // W_proj^T fp16 [N][K]

__device__ __forceinline__ uint32_t f2h2(float lo, float hi) {
    __half2 h = __floats2half2_rn(lo, hi);
    return *reinterpret_cast<uint32_t*>(&h);
}

__device__ __forceinline__ void mma_f16(float* c, const uint32_t* a, const uint32_t* b) {
    asm volatile(
        "mma.sync.aligned.m16n8k16.row.col.f32.f16.f16.f32 "
        "{%0,%1,%2,%3}, {%4,%5,%6,%7}, {%8,%9}, {%0,%1,%2,%3};\n"
        : "+f"(c[0]), "+f"(c[1]), "+f"(c[2]), "+f"(c[3])
        : "r"(a[0]), "r"(a[1]), "r"(a[2]), "r"(a[3]), "r"(b[0]), "r"(b[1]));
}

#define CP_ASYNC16(dst_u32, src) \
    asm volatile("cp.async.cg.shared.global [%0], [%1], 16;\n" :: "r"(dst_u32), "l"(src))
#define CP_COMMIT() asm volatile("cp.async.commit_group;\n" ::: "memory")
#define CP_WAIT0()  asm volatile("cp.async.wait_group 0;\n" ::: "memory")

// ---------------------------------------------------------------------------
// x fp32 -> fp16
// ---------------------------------------------------------------------------
__global__ __launch_bounds__(256)
void convert_x(const float* __restrict__ x, __half* __restrict__ x16) {
    const long i = ((long)blockIdx.x * 256 + threadIdx.x) * 4;
    float4 v = *(const float4*)(x + i);
    uint2 u;
    u.x = f2h2(v.x, v.y);
    u.y = f2h2(v.z, v.w);
    *(uint2*)(x16 + i) = u;
}

// ---------------------------------------------------------------------------
// Weight transpose + fp16 convert: Wt16[n][k] = (half)W[k][n]
// ---------------------------------------------------------------------------
__global__ __launch_bounds__(256)
void transpose_w_h(const float* __restrict__ W, __half* __restrict__ Wt, int K, int N) {
    __shared__ float t[32][33];
    const int n0 = blockIdx.x * 32, k0 = blockIdx.y * 32;
    const int x = threadIdx.x & 31, y = threadIdx.x >> 5;
#pragma unroll
    for (int i = 0; i < 4; i++)
        t[y + 8 * i][x] = W[(long)(k0 + y + 8 * i) * N + n0 + x];
    __syncthreads();
#pragma unroll
    for (int i = 0; i < 4; i++)
        Wt[(long)(n0 + y + 8 * i) * K + k0 + x] = __float2half_rn(t[x][y + 8 * i]);
}

// ---------------------------------------------------------------------------
// FP16 GEMM with bias, cp.async 2-stage: C = A[M,K] @ Bt[N,K]^T + bias.
// 256 thr, 8 warps (4x2), 128x128 tile, BK=32. out16: write half, else float.
// Smem rows: 40 halves (20-word pitch); frag words gid*20+tig -> 32 banks.
// ---------------------------------------------------------------------------
#define AP 20

__global__ __launch_bounds__(256, 2)
void h16_gemm_bias(const __half* __restrict__ A, const __half* __restrict__ Bt,
                   const float* __restrict__ bias, void* __restrict__ CoutV,
                   int M, int N, int K, int out16) {
    __shared__ uint32_t As[2][128 * AP];
    __shared__ uint32_t Bs[2][128 * AP];

    const int tid = threadIdx.x;
    const int lane = tid & 31;
    const int warp = tid >> 5;
    const int gid = lane >> 2;
    const int tig = lane & 3;
    const int wm = warp >> 1;
    const int wn = warp & 1;
    const int m0w = wm * 32;
    const int n0w = wn * 64;
    const int br = blockIdx.y * 128;
    const int bc = blockIdx.x * 128;

    // cp.async chunk mapping: 512 16B-chunks per tensor, 2 per thread
    const int c0 = tid, c1 = tid + 256;
    const int r0c = c0 >> 2, o0c = c0 & 3;
    const int r1c = c1 >> 2, o1c = c1 & 3;
    const uint32_t as_b = (uint32_t)__cvta_generic_to_shared(&As[0][0]);
    const uint32_t bs_b = (uint32_t)__cvta_generic_to_shared(&Bs[0][0]);

    const __half* A0 = A + (long)(br + r0c) * K + o0c * 8;
    const __half* A1 = A + (long)(br + r1c) * K + o1c * 8;
    const __half* B0 = Bt + (long)(bc + r0c) * K + o0c * 8;
    const __half* B1 = Bt + (long)(bc + r1c) * K + o1c * 8;

    float c[2][8][4];
#pragma unroll
    for (int mi = 0; mi < 2; mi++)
#pragma unroll
        for (int nj = 0; nj < 8; nj++)
#pragma unroll
            for (int e = 0; e < 4; e++) c[mi][nj][e] = 0.f;

    // prologue: issue chunk 0 -> stage 0
    CP_ASYNC16(as_b + r0c * 80 + o0c * 16, A0);
    CP_ASYNC16(as_b + r1c * 80 + o1c * 16, A1);
    CP_ASYNC16(bs_b + r0c * 80 + o0c * 16, B0);
    CP_ASYNC16(bs_b + r1c * 80 + o1c * 16, B1);
    CP_COMMIT();

    int st = 0;
    const int nch = K >> 5;
    for (int ch = 0; ch < nch; ch++) {
        CP_WAIT0();
        __syncthreads();

        if (ch + 1 < nch) {
            const int s2 = (st ^ 1) * 10240;
            CP_ASYNC16(as_b + s2 + r0c * 80 + o0c * 16, A0 + (ch + 1) * 32);
            CP_ASYNC16(as_b + s2 + r1c * 80 + o1c * 16, A1 + (ch + 1) * 32);
            CP_ASYNC16(bs_b + s2 + r0c * 80 + o0c * 16, B0 + (ch + 1) * 32);
            CP_ASYNC16(bs_b + s2 + r1c * 80 + o1c * 16, B1 + (ch + 1) * 32);
            CP_COMMIT();
        }

#pragma unroll
        for (int ks = 0; ks < 2; ks++) {
            uint32_t a[2][4];
#pragma unroll
            for (int mi = 0; mi < 2; mi++) {
                int base = (m0w + mi * 16 + gid) * AP + ks * 8 + tig;
                a[mi][0] = As[st][base];
                a[mi][1] = As[st][base + 8 * AP];
                a[mi][2] = As[st][base + 4];
                a[mi][3] = As[st][base + 8 * AP + 4];
            }
#pragma unroll
            for (int nj = 0; nj < 8; nj++) {
                uint32_t b[2];
                int base = (n0w + nj * 8 + gid) * AP + ks * 8 + tig;
                b[0] = Bs[st][base];
                b[1] = Bs[st][base + 4];
                mma_f16(c[0][nj], a[0], b);
                mma_f16(c[1][nj], a[1], b);
            }
        }
        st ^= 1;
    }

    // epilogue
#pragma unroll
    for (int mi = 0; mi < 2; mi++) {
        int row = br + m0w + mi * 16 + gid;
#pragma unroll
        for (int nj = 0; nj < 8; nj++) {
            int col = bc + n0w + nj * 8 + tig * 2;
            float2 bb = *(const float2*)(bias + col);
            float o00 = c[mi][nj][0] + bb.x, o01 = c[mi][nj][1] + bb.y;
            float o10 = c[mi][nj][2] + bb.x, o11 = c[mi][nj][3] + bb.y;
            if (out16) {
                __half* Ch = (__half*)CoutV;
                *(uint32_t*)(Ch + (long)row * N + col) = f2h2(o00, o01);
                *(uint32_t*)(Ch + (long)(row + 8) * N + col) = f2h2(o10, o11);
            } else {
                float* Cf = (float*)CoutV;
                *(float2*)(Cf + (long)row * N + col) = make_float2(o00, o01);
                *(float2*)(Cf + (long)(row + 8) * N + col) = make_float2(o10, o11);
            }
        }
    }
}

// ---------------------------------------------------------------------------
// Fused per-head RMSNorm + RoPE on q,k of g_qkv16 (fp16 in/out, fp32 math).
// ---------------------------------------------------------------------------
__global__ __launch_bounds__(256)
void norm_rope16_kernel(__half* __restrict__ qkv,
                        const float* __restrict__ cosb,
                        const float* __restrict__ sinb) {
    __shared__ float qn[1024];
    __shared__ float kn[1024];
    const int bt = blockIdx.x;
    const int t = bt & (TT - 1);
    const int tid = threadIdx.x;
    __half* qrow = qkv + (long)bt * 3072;
    __half* krow = qrow + 1024;

    const int i = tid * 4;
    uint2 qu = *(const uint2*)(qrow + i);
    uint2 ku = *(const uint2*)(krow + i);
    float2 q01 = __half22float2(*(__half2*)&qu.x);
    float2 q23 = __half22float2(*(__half2*)&qu.y);
    float2 k01 = __half22float2(*(__half2*)&ku.x);
    float2 k23 = __half22float2(*(__half2*)&ku.y);

    float qs = q01.x * q01.x + q01.y * q01.y + q23.x * q23.x + q23.y * q23.y;
    float ks = k01.x * k01.x + k01.y * k01.y + k23.x * k23.x + k23.y * k23.y;
#pragma unroll
    for (int o = 8; o > 0; o >>= 1) {
        qs += __shfl_xor_sync(0xffffffffu, qs, o);
        ks += __shfl_xor_sync(0xffffffffu, ks, o);
    }
    const float qsc = rsqrtf(qs * (1.f / 64.f) + 1.1920929e-07f);
    const float ksc = rsqrtf(ks * (1.f / 64.f) + 1.1920929e-07f);
    qn[i + 0] = q01.x * qsc; qn[i + 1] = q01.y * qsc;
    qn[i + 2] = q23.x * qsc; qn[i + 3] = q23.y * qsc;
    kn[i + 0] = k01.x * ksc; kn[i + 1] = k01.y * ksc;
    kn[i + 2] = k23.x * ksc; kn[i + 3] = k23.y * ksc;
    __syncthreads();

    const int d = i & 63;
    const int base = i - d;
    float4 cv = *(const float4*)(cosb + t * 64 + d);
    float4 sv = *(const float4*)(sinb + t * 64 + d);
    float rq[4], rk[4];
    if (d < 32) {
#pragma unroll
        for (int j = 0; j < 4; j++) {
            rq[j] = -qn[base + d + 32 + j];
            rk[j] = -kn[base + d + 32 + j];
        }
    } else {
#pragma unroll
        for (int j = 0; j < 4; j++) {
            rq[j] = qn[base + d - 32 + j];
            rk[j] = kn[base + d - 32 + j];
        }
    }
    float cc[4] = {cv.x, cv.y, cv.z, cv.w};
    float ss[4] = {sv.x, sv.y, sv.z, sv.w};
    float oq[4], ok[4];
#pragma unroll
    for (int j = 0; j < 4; j++) {
        oq[j] = qn[i + j] * cc[j] + rq[j] * ss[j];
        ok[j] = kn[i + j] * cc[j] + rk[j] * ss[j];
    }
    uint2 qo, ko;
    qo.x = f2h2(oq[0], oq[1]); qo.y = f2h2(oq[2], oq[3]);
    ko.x = f2h2(ok[0], ok[1]); ko.y = f2h2(ok[2], ok[3]);
    *(uint2*)(qrow + i) = qo;
    *(uint2*)(krow + i) = ko;
}

// ---------------------------------------------------------------------------
// FP16 flash attention, fixed-max softmax, cp.async double-buffered K/V.
// 256 thr, 8 warps x 16 rows, BKV=64. Smem (words): Ks[2][2304] Vs[2][2304]
// Ps[4608]; pitch 36 words (72 halves). 55.3 KB -> 2 CTA/SM.
// ---------------------------------------------------------------------------
#define TPW 36
#define ATT_SMEM ((2 * 2304 * 2 + 4608) * 4)

__global__ __launch_bounds__(256, 2)
void attn_h16_kernel(const __half* __restrict__ qkv, __half* __restrict__ y) {
    extern __shared__ uint32_t smu[];
    uint32_t* Ps = smu + 9216;           // [128][TPW]
    const uint32_t smb = (uint32_t)__cvta_generic_to_shared(smu);
    const uint32_t ks_b = smb;           // K stages at bytes 0 / 9216
    const uint32_t vs_b = smb + 18432;   // V stages at bytes 18432 / 27648

    const int qb = (int)(gridDim.x - 1) - (int)blockIdx.x;  // heavy CTAs first
    const int h = blockIdx.y, b = blockIdx.z;
    const int tid = threadIdx.x;
    const int lane = tid & 31, warp = tid >> 5;
    const int gid = lane >> 2, tig = lane & 3;
    const int r0 = warp * 16;

    // cp.async mapping: 512 chunks per tensor, 2 per thread
    const int kc0 = tid * 2, kc1 = tid * 2 + 1;
    const int krow0 = kc0 >> 3, ko0 = kc0 & 7;
    const int krow1 = kc1 >> 3, ko1 = kc1 & 7;
    const long kvb0 = ((long)(b * TT + krow0) * 3) * 1024 + h * 64 + ko0 * 8;
    const long kvb1 = ((long)(b * TT + krow1) * 3) * 1024 + h * 64 + ko1 * 8;
    const uint32_t kd0 = (uint32_t)(krow0 * 144 + ko0 * 16);
    const uint32_t kd1 = (uint32_t)(krow1 * 144 + ko1 * 16);

    // ---- prologue: issue KV tile 0 -> stage 0 ----
    {
        const __half* s0 = qkv + kvb0 + 1024;
        const __half* s1 = qkv + kvb1 + 1024;
        CP_ASYNC16(ks_b + kd0, s0);
        CP_ASYNC16(ks_b + kd1, s1);
        CP_ASYNC16(vs_b + kd0, s0 + 1024);
        CP_ASYNC16(vs_b + kd1, s1 + 1024);
        CP_COMMIT();
    }

    // ---- stage Q (x 1/8 exact) into Ps; load A-fragments ----
    {
        const __half2 qscale = __floats2half2_rn(0.125f, 0.125f);
        const int row = tid >> 1;
        const int dh = (tid & 1) * 32;
        const uint4* src = (const uint4*)(qkv + ((long)(b * TT + qb * 128 + row) * 3) * 1024 + h * 64 + dh);
#pragma unroll
        for (int j = 0; j < 4; j++) {
            uint4 u = src[j];
            __half2* hp = (__half2*)&u;
            hp[0] = __hmul2(hp[0], qscale);
            hp[1] = __hmul2(hp[1], qscale);
            hp[2] = __hmul2(hp[2], qscale);
            hp[3] = __hmul2(hp[3], qscale);
            *(uint4*)&Ps[row * TPW + (tid & 1) * 16 + j * 4] = u;
        }
    }
    __syncthreads();
    uint32_t qa[4][4];
#pragma unroll
    for (int ks = 0; ks < 4; ks++) {
        int base = (r0 + gid) * TPW + ks * 8 + tig;
        qa[ks][0] = Ps[base];
        qa[ks][1] = Ps[base + 8 * TPW];
        qa[ks][2] = Ps[base + 4];
        qa[ks][3] = Ps[base + 8 * TPW + 4];
    }

    float cO[8][4];
#pragma unroll
    for (int nj = 0; nj < 8; nj++)
#pragma unroll
        for (int e = 0; e < 4; e++) cO[nj][e] = 0.f;
    float lp0 = 0.f, lp1 = 0.f;

    const int nkv = 2 * (qb + 1);
    int st = 0;
    for (int kb = 0; kb < nkv; kb++) {
        CP_WAIT0();
        __syncthreads();   // tile kb landed everywhere; prev math done

        if (kb + 1 < nkv) {
            const uint32_t so = (uint32_t)((st ^ 1) * 9216);
            const __half* s0 = qkv + kvb0 + (long)(kb + 1) * 64 * 3072 + 1024;
            const __half* s1 = qkv + kvb1 + (long)(kb + 1) * 64 * 3072 + 1024;
            CP_ASYNC16(ks_b + so + kd0, s0);
            CP_ASYNC16(ks_b + so + kd1, s1);
            CP_ASYNC16(vs_b + so + kd0, s0 + 1024);
            CP_ASYNC16(vs_b + so + kd1, s1 + 1024);
            CP_COMMIT();
        }

        const uint32_t* Kc = smu + st * 2304;
        const uint32_t vrb = vs_b + (uint32_t)(st * 9216);

        // ---- S = Q @ K^T ----
        float cS[8][4];
#pragma unroll
        for (int nj = 0; nj < 8; nj++)
#pragma unroll
            for (int e = 0; e < 4; e++) cS[nj][e] = 0.f;

#pragma unroll
        for (int ks = 0; ks < 4; ks++) {
#pragma unroll
            for (int nj = 0; nj < 8; nj++) {
                uint32_t bb[2];
                int base = (nj * 8 + gid) * TPW + ks * 8 + tig;
                bb[0] = Kc[base];
                bb[1] = Kc[base + 4];
                mma_f16(cS[nj], qa[ks], bb);
            }
        }

        if (kb >= 2 * qb) {  // causal diagonal tiles
            int rA = qb * 128 + r0 + gid;
            int rB = rA + 8;
#pragma unroll
            for (int nj = 0; nj < 8; nj++) {
                int col = kb * 64 + nj * 8 + 2 * tig;
                if (col     > rA) cS[nj][0] = -3.0e38f;
                if (col + 1 > rA) cS[nj][1] = -3.0e38f;
                if (col     > rB) cS[nj][2] = -3.0e38f;
                if (col + 1 > rB) cS[nj][3] = -3.0e38f;
            }
        }

        // ---- fixed-max softmax: p = exp(s - 8) ----
#pragma unroll
        for (int nj = 0; nj < 8; nj++) {
            cS[nj][0] = __expf(cS[nj][0] - 8.0f); lp0 += cS[nj][0];
            cS[nj][1] = __expf(cS[nj][1] - 8.0f); lp0 += cS[nj][1];
            cS[nj][2] = __expf(cS[nj][2] - 8.0f); lp1 += cS[nj][2];
            cS[nj][3] = __expf(cS[nj][3] - 8.0f); lp1 += cS[nj][3];
        }

        // ---- store P (fp16); warp-private rows ----
#pragma unroll
        for (int nj = 0; nj < 8; nj++) {
            Ps[(r0 + gid) * TPW + nj * 4 + tig]     = f2h2(cS[nj][0], cS[nj][1]);
            Ps[(r0 + gid + 8) * TPW + nj * 4 + tig] = f2h2(cS[nj][2], cS[nj][3]);
        }
        __syncwarp();

        // ---- O += P @ V (V frags via ldmatrix.x2.trans) ----
#pragma unroll
        for (int ks = 0; ks < 4; ks++) {
            uint32_t pa[4];
            int abase = (r0 + gid) * TPW + ks * 8 + tig;
            pa[0] = Ps[abase];
            pa[1] = Ps[abase + 8 * TPW];
            pa[2] = Ps[abase + 4];
            pa[3] = Ps[abase + 8 * TPW + 4];
            const uint32_t vrow = vrb + (uint32_t)((ks * 16 + (lane & 15)) * 144);
#pragma unroll
            for (int nj = 0; nj < 8; nj++) {
                uint32_t bb0, bb1;
                asm volatile(
                    "ldmatrix.sync.aligned.m8n8.x2.trans.shared.b16 {%0,%1}, [%2];"
                    : "=r"(bb0), "=r"(bb1) : "r"(vrow + nj * 16));
                uint32_t bb[2] = {bb0, bb1};
                mma_f16(cO[nj], pa, bb);
            }
        }
        st ^= 1;
    }

    // ---- final row-sum reduction + epilogue (fp16 y) ----
    lp0 += __shfl_xor_sync(0xffffffffu, lp0, 1);
    lp0 += __shfl_xor_sync(0xffffffffu, lp0, 2);
    lp1 += __shfl_xor_sync(0xffffffffu, lp1, 1);
    lp1 += __shfl_xor_sync(0xffffffffu, lp1, 2);
    float inv0 = 1.0f / lp0, inv1 = 1.0f / lp1;
    long rowA = (long)(b * TT + qb * 128 + r0 + gid) * 1024 + h * 64;
    long rowB = rowA + 8 * 1024;
#pragma unroll
    for (int nj = 0; nj < 8; nj++) {
        int col = nj * 8 + 2 * tig;
        *(uint32_t*)(y + rowA + col) = f2h2(cO[nj][0] * inv0, cO[nj][1] * inv0);
        *(uint32_t*)(y + rowB + col) = f2h2(cO[nj][2] * inv1, cO[nj][3] * inv1);
    }
}

// ---------------------------------------------------------------------------
extern "C" void kernel_launch(void* const* d_in, const int* in_sizes, int n_in,
                              void* d_out, int out_size) {
    const float* x      = (const float*)d_in[0];
    const float* cosb   = (const float*)d_in[1];
    const float* sinb   = (const float*)d_in[2];
    const float* W_attn = (const float*)d_in[3];
    const float* b_attn = (const float*)d_in[4];
    const float* W_proj = (const float*)d_in[5];
    const float* b_proj = (const float*)d_in[6];
    float* out = (float*)d_out;

    __half *x16, *qkv16, *y16, *wta, *wtp;
    cudaGetSymbolAddress((void**)&x16, g_x16);
    cudaGetSymbolAddress((void**)&qkv16, g_qkv16);
    cudaGetSymbolAddress((void**)&y16, g_y16);
    cudaGetSymbolAddress((void**)&wta, g_wta16);
    cudaGetSymbolAddress((void**)&wtp, g_wtp16);

    // 0) converts: x -> fp16; weights -> fp16 [N][K]
    convert_x<<<4096, 256>>>(x, x16);
    transpose_w_h<<<dim3(96, 32), 256>>>(W_attn, wta, 1024, 3072);
    transpose_w_h<<<dim3(32, 32), 256>>>(W_proj, wtp, 1024, 1024);

    // 1) QKV GEMM (fp16, cp.async): -> g_qkv16
    h16_gemm_bias<<<dim3(3072 / 128, 4096 / 128), 256>>>(x16, wta, b_attn, qkv16, 4096, 3072, 1024, 1);

    // 2) per-head RMSNorm + RoPE on q,k (fp16 in place)
    norm_rope16_kernel<<<2 * TT, 256>>>(qkv16, cosb, sinb);

    // 3) causal flash attention (fp16, cp.async KV, fixed-max softmax)
    cudaFuncSetAttribute(attn_h16_kernel, cudaFuncAttributeMaxDynamicSharedMemorySize, ATT_SMEM);
    attn_h16_kernel<<<dim3(TT / 128, 16, 2), 256, ATT_SMEM>>>(qkv16, y16);

    // 4) output projection (fp16, cp.async): -> fp32 out
    h16_gemm_bias<<<dim3(1024 / 128, 4096 / 128), 256>>>(y16, wtp, b_proj, out, 4096, 1024, 1024, 0);
}

// round 14
// speedup vs baseline: 2.1814x; 1.0070x over previous
#include <cuda_runtime.h>
#include <cuda_fp16.h>
#include <cstdint>

// Problem constants: B=2, T=2048, C=1024, H=16, D=64
#define TT 2048

// Scratch (allocation-free rule: __device__ globals)
__device__ __half g_x16[2 * 2048 * 1024];        // x fp16
__device__ __half g_qkv16[2 * 2048 * 3 * 1024];  // [B,T,3,H,D] fp16
__device__ __half g_y16[2 * 2048 * 1024];        // [B,T,H,D] fp16
__device__ __half g_wta16[3072 * 1024];          // W_attn^T fp16 [N][K]
__device__ __half g_wtp16[1024 * 1024];          // W_proj^T fp16 [N][K]

__device__ __forceinline__ uint32_t f2h2(float lo, float hi) {
    __half2 h = __floats2half2_rn(lo, hi);
    return *reinterpret_cast<uint32_t*>(&h);
}

__device__ __forceinline__ void mma_f16(float* c, const uint32_t* a, const uint32_t* b) {
    asm volatile(
        "mma.sync.aligned.m16n8k16.row.col.f32.f16.f16.f32 "
        "{%0,%1,%2,%3}, {%4,%5,%6,%7}, {%8,%9}, {%0,%1,%2,%3};\n"
        : "+f"(c[0]), "+f"(c[1]), "+f"(c[2]), "+f"(c[3])
        : "r"(a[0]), "r"(a[1]), "r"(a[2]), "r"(a[3]), "r"(b[0]), "r"(b[1]));
}

#define CP_ASYNC16(dst_u32, src) \
    asm volatile("cp.async.cg.shared.global [%0], [%1], 16;\n" :: "r"(dst_u32), "l"(src))
#define CP_COMMIT() asm volatile("cp.async.commit_group;\n" ::: "memory")
#define CP_WAIT2()  asm volatile("cp.async.wait_group 2;\n" ::: "memory")

// ---------------------------------------------------------------------------
// x fp32 -> fp16
// ---------------------------------------------------------------------------
__global__ __launch_bounds__(256)
void convert_x(const float* __restrict__ x, __half* __restrict__ x16) {
    const long i = ((long)blockIdx.x * 256 + threadIdx.x) * 4;
    float4 v = *(const float4*)(x + i);
    uint2 u;
    u.x = f2h2(v.x, v.y);
    u.y = f2h2(v.z, v.w);
    *(uint2*)(x16 + i) = u;
}

// ---------------------------------------------------------------------------
// Weight transpose + fp16 convert: Wt16[n][k] = (half)W[k][n]
// ---------------------------------------------------------------------------
__global__ __launch_bounds__(256)
void transpose_w_h(const float* __restrict__ W, __half* __restrict__ Wt, int K, int N) {
    __shared__ float t[32][33];
    const int n0 = blockIdx.x * 32, k0 = blockIdx.y * 32;
    const int x = threadIdx.x & 31, y = threadIdx.x >> 5;
#pragma unroll
    for (int i = 0; i < 4; i++)
        t[y + 8 * i][x] = W[(long)(k0 + y + 8 * i) * N + n0 + x];
    __syncthreads();
#pragma unroll
    for (int i = 0; i < 4; i++)
        Wt[(long)(n0 + y + 8 * i) * K + k0 + x] = __float2half_rn(t[x][y + 8 * i]);
}

// ---------------------------------------------------------------------------
// FP16 GEMM with bias, cp.async 4-stage pipeline: C = A @ Bt^T + bias.
// 256 thr, 8 warps (4x2), 128x128 tile, BK=32.
// Dynamic smem ring: A stages [4][2560 w], B stages [4][2560 w] = 80 KB.
// Row pitch 20 words (40 halves); frag words gid*20+tig -> all 32 banks.
// ---------------------------------------------------------------------------
#define AP 20
#define GST 2560                      // words per stage per tensor
#define GEMM_SMEM (8 * GST * 4)       // 4 stages x (A+B) x 4B

__global__ __launch_bounds__(256, 2)
void h16_gemm_bias(const __half* __restrict__ A, const __half* __restrict__ Bt,
                   const float* __restrict__ bias, void* __restrict__ CoutV,
                   int M, int N, int K, int out16) {
    extern __shared__ uint32_t gsm[];
    const uint32_t smb = (uint32_t)__cvta_generic_to_shared(gsm);

    const int tid = threadIdx.x;
    const int lane = tid & 31;
    const int warp = tid >> 5;
    const int gid = lane >> 2;
    const int tig = lane & 3;
    const int wm = warp >> 1;
    const int wn = warp & 1;
    const int m0w = wm * 32;
    const int n0w = wn * 64;
    const int br = blockIdx.y * 128;
    const int bc = blockIdx.x * 128;

    // cp.async chunk mapping: 512 16B-chunks per tensor, 2 per thread
    const int r0c = tid >> 2, o0c = tid & 3;
    const int r1c = (tid + 256) >> 2, o1c = tid & 3;
    const uint32_t ad0 = (uint32_t)(r0c * 80 + o0c * 16);
    const uint32_t ad1 = (uint32_t)(r1c * 80 + o1c * 16);

    const __half* A0 = A + (long)(br + r0c) * K + o0c * 8;
    const __half* A1 = A + (long)(br + r1c) * K + o1c * 8;
    const __half* B0 = Bt + (long)(bc + r0c) * K + o0c * 8;
    const __half* B1 = Bt + (long)(bc + r1c) * K + o1c * 8;

    float c[2][8][4];
#pragma unroll
    for (int mi = 0; mi < 2; mi++)
#pragma unroll
        for (int nj = 0; nj < 8; nj++)
#pragma unroll
            for (int e = 0; e < 4; e++) c[mi][nj][e] = 0.f;

    const int nch = K >> 5;
    // ---- prologue: issue chunks 0..2 into stages 0..2 ----
#pragma unroll
    for (int p = 0; p < 3; p++) {
        const uint32_t as_s = smb + (uint32_t)(p * GST * 4);
        const uint32_t bs_s = smb + (uint32_t)((4 + p) * GST * 4);
        CP_ASYNC16(as_s + ad0, A0 + p * 32);
        CP_ASYNC16(as_s + ad1, A1 + p * 32);
        CP_ASYNC16(bs_s + ad0, B0 + p * 32);
        CP_ASYNC16(bs_s + ad1, B1 + p * 32);
        CP_COMMIT();
    }

    for (int ch = 0; ch < nch; ch++) {
        CP_WAIT2();          // group for chunk ch complete (uniform commits)
        __syncthreads();

        const int ci = ch + 3;
        if (ci < nch) {
            const uint32_t as_s = smb + (uint32_t)((ci & 3) * GST * 4);
            const uint32_t bs_s = smb + (uint32_t)((4 + (ci & 3)) * GST * 4);
            CP_ASYNC16(as_s + ad0, A0 + ci * 32);
            CP_ASYNC16(as_s + ad1, A1 + ci * 32);
            CP_ASYNC16(bs_s + ad0, B0 + ci * 32);
            CP_ASYNC16(bs_s + ad1, B1 + ci * 32);
        }
        CP_COMMIT();         // always commit (empty groups keep accounting)

        const uint32_t* As = gsm + (ch & 3) * GST;
        const uint32_t* Bs = gsm + (4 + (ch & 3)) * GST;
#pragma unroll
        for (int ks = 0; ks < 2; ks++) {
            uint32_t a[2][4];
#pragma unroll
            for (int mi = 0; mi < 2; mi++) {
                int base = (m0w + mi * 16 + gid) * AP + ks * 8 + tig;
                a[mi][0] = As[base];
                a[mi][1] = As[base + 8 * AP];
                a[mi][2] = As[base + 4];
                a[mi][3] = As[base + 8 * AP + 4];
            }
#pragma unroll
            for (int nj = 0; nj < 8; nj++) {
                uint32_t b[2];
                int base = (n0w + nj * 8 + gid) * AP + ks * 8 + tig;
                b[0] = Bs[base];
                b[1] = Bs[base + 4];
                mma_f16(c[0][nj], a[0], b);
                mma_f16(c[1][nj], a[1], b);
            }
        }
    }

    // epilogue
#pragma unroll
    for (int mi = 0; mi < 2; mi++) {
        int row = br + m0w + mi * 16 + gid;
#pragma unroll
        for (int nj = 0; nj < 8; nj++) {
            int col = bc + n0w + nj * 8 + tig * 2;
            float2 bb = *(const float2*)(bias + col);
            float o00 = c[mi][nj][0] + bb.x, o01 = c[mi][nj][1] + bb.y;
            float o10 = c[mi][nj][2] + bb.x, o11 = c[mi][nj][3] + bb.y;
            if (out16) {
                __half* Ch = (__half*)CoutV;
                *(uint32_t*)(Ch + (long)row * N + col) = f2h2(o00, o01);
                *(uint32_t*)(Ch + (long)(row + 8) * N + col) = f2h2(o10, o11);
            } else {
                float* Cf = (float*)CoutV;
                *(float2*)(Cf + (long)row * N + col) = make_float2(o00, o01);
                *(float2*)(Cf + (long)(row + 8) * N + col) = make_float2(o10, o11);
            }
        }
    }
}

// ---------------------------------------------------------------------------
// Fused per-head RMSNorm + RoPE on q,k of g_qkv16 (fp16 in/out, fp32 math).
// ---------------------------------------------------------------------------
__global__ __launch_bounds__(256)
void norm_rope16_kernel(__half* __restrict__ qkv,
                        const float* __restrict__ cosb,
                        const float* __restrict__ sinb) {
    __shared__ float qn[1024];
    __shared__ float kn[1024];
    const int bt = blockIdx.x;
    const int t = bt & (TT - 1);
    const int tid = threadIdx.x;
    __half* qrow = qkv + (long)bt * 3072;
    __half* krow = qrow + 1024;

    const int i = tid * 4;
    uint2 qu = *(const uint2*)(qrow + i);
    uint2 ku = *(const uint2*)(krow + i);
    float2 q01 = __half22float2(*(__half2*)&qu.x);
    float2 q23 = __half22float2(*(__half2*)&qu.y);
    float2 k01 = __half22float2(*(__half2*)&ku.x);
    float2 k23 = __half22float2(*(__half2*)&ku.y);

    float qs = q01.x * q01.x + q01.y * q01.y + q23.x * q23.x + q23.y * q23.y;
    float ks = k01.x * k01.x + k01.y * k01.y + k23.x * k23.x + k23.y * k23.y;
#pragma unroll
    for (int o = 8; o > 0; o >>= 1) {
        qs += __shfl_xor_sync(0xffffffffu, qs, o);
        ks += __shfl_xor_sync(0xffffffffu, ks, o);
    }
    const float qsc = rsqrtf(qs * (1.f / 64.f) + 1.1920929e-07f);
    const float ksc = rsqrtf(ks * (1.f / 64.f) + 1.1920929e-07f);
    qn[i + 0] = q01.x * qsc; qn[i + 1] = q01.y * qsc;
    qn[i + 2] = q23.x * qsc; qn[i + 3] = q23.y * qsc;
    kn[i + 0] = k01.x * ksc; kn[i + 1] = k01.y * ksc;
    kn[i + 2] = k23.x * ksc; kn[i + 3] = k23.y * ksc;
    __syncthreads();

    const int d = i & 63;
    const int base = i - d;
    float4 cv = *(const float4*)(cosb + t * 64 + d);
    float4 sv = *(const float4*)(sinb + t * 64 + d);
    float rq[4], rk[4];
    if (d < 32) {
#pragma unroll
        for (int j = 0; j < 4; j++) {
            rq[j] = -qn[base + d + 32 + j];
            rk[j] = -kn[base + d + 32 + j];
        }
    } else {
#pragma unroll
        for (int j = 0; j < 4; j++) {
            rq[j] = qn[base + d - 32 + j];
            rk[j] = kn[base + d - 32 + j];
        }
    }
    float cc[4] = {cv.x, cv.y, cv.z, cv.w};
    float ss[4] = {sv.x, sv.y, sv.z, sv.w};
    float oq[4], ok[4];
#pragma unroll
    for (int j = 0; j < 4; j++) {
        oq[j] = qn[i + j] * cc[j] + rq[j] * ss[j];
        ok[j] = kn[i + j] * cc[j] + rk[j] * ss[j];
    }
    uint2 qo, ko;
    qo.x = f2h2(oq[0], oq[1]); qo.y = f2h2(oq[2], oq[3]);
    ko.x = f2h2(ok[0], ok[1]); ko.y = f2h2(ok[2], ok[3]);
    *(uint2*)(qrow + i) = qo;
    *(uint2*)(krow + i) = ko;
}

// ---------------------------------------------------------------------------
// FP16 flash attention, fixed-max softmax, cp.async 4-stage K/V pipeline.
// 256 thr, 8 warps x 16 rows, BKV=64. Smem words: K[4][2304] V[4][2304]
// Ps[4608] -> 92160 B; 2 CTA/SM.
// ---------------------------------------------------------------------------
#define TPW 36
#define AST 2304                          // words per K (or V) stage
#define ATT_SMEM ((8 * AST + 4608) * 4)

__global__ __launch_bounds__(256, 2)
void attn_h16_kernel(const __half* __restrict__ qkv, __half* __restrict__ y) {
    extern __shared__ uint32_t smu[];
    uint32_t* Ps = smu + 8 * AST;         // [128][TPW]
    const uint32_t smb = (uint32_t)__cvta_generic_to_shared(smu);
    const uint32_t vs_b0 = smb + 4 * AST * 4;

    const int qb = (int)(gridDim.x - 1) - (int)blockIdx.x;  // heavy CTAs first
    const int h = blockIdx.y, b = blockIdx.z;
    const int tid = threadIdx.x;
    const int lane = tid & 31, warp = tid >> 5;
    const int gid = lane >> 2, tig = lane & 3;
    const int r0 = warp * 16;

    // cp.async mapping: 512 chunks per tensor, 2 per thread
    const int kc0 = tid * 2, kc1 = tid * 2 + 1;
    const int krow0 = kc0 >> 3, ko0 = kc0 & 7;
    const int krow1 = kc1 >> 3, ko1 = kc1 & 7;
    const long kvb0 = ((long)(b * TT + krow0) * 3) * 1024 + h * 64 + ko0 * 8;
    const long kvb1 = ((long)(b * TT + krow1) * 3) * 1024 + h * 64 + ko1 * 8;
    const uint32_t kd0 = (uint32_t)(krow0 * 144 + ko0 * 16);
    const uint32_t kd1 = (uint32_t)(krow1 * 144 + ko1 * 16);

    const int nkv = 2 * (qb + 1);

    // ---- prologue: issue tiles 0..2 (guarded; uniform commits) ----
#pragma unroll
    for (int p = 0; p < 3; p++) {
        if (p < nkv) {
            const uint32_t ko = (uint32_t)(p * AST * 4);
            const __half* s0 = qkv + kvb0 + (long)p * 64 * 3072 + 1024;
            const __half* s1 = qkv + kvb1 + (long)p * 64 * 3072 + 1024;
            CP_ASYNC16(smb + ko + kd0, s0);
            CP_ASYNC16(smb + ko + kd1, s1);
            CP_ASYNC16(vs_b0 + ko + kd0, s0 + 1024);
            CP_ASYNC16(vs_b0 + ko + kd1, s1 + 1024);
        }
        CP_COMMIT();
    }

    // ---- stage Q (x 1/8 exact) into Ps; load A-fragments ----
    {
        const __half2 qscale = __floats2half2_rn(0.125f, 0.125f);
        const int row = tid >> 1;
        const int dh = (tid & 1) * 32;
        const uint4* src = (const uint4*)(qkv + ((long)(b * TT + qb * 128 + row) * 3) * 1024 + h * 64 + dh);
#pragma unroll
        for (int j = 0; j < 4; j++) {
            uint4 u = src[j];
            __half2* hp = (__half2*)&u;
            hp[0] = __hmul2(hp[0], qscale);
            hp[1] = __hmul2(hp[1], qscale);
            hp[2] = __hmul2(hp[2], qscale);
            hp[3] = __hmul2(hp[3], qscale);
            *(uint4*)&Ps[row * TPW + (tid & 1) * 16 + j * 4] = u;
        }
    }
    __syncthreads();
    uint32_t qa[4][4];
#pragma unroll
    for (int ks = 0; ks < 4; ks++) {
        int base = (r0 + gid) * TPW + ks * 8 + tig;
        qa[ks][0] = Ps[base];
        qa[ks][1] = Ps[base + 8 * TPW];
        qa[ks][2] = Ps[base + 4];
        qa[ks][3] = Ps[base + 8 * TPW + 4];
    }

    float cO[8][4];
#pragma unroll
    for (int nj = 0; nj < 8; nj++)
#pragma unroll
        for (int e = 0; e < 4; e++) cO[nj][e] = 0.f;
    float lp0 = 0.f, lp1 = 0.f;

    for (int kb = 0; kb < nkv; kb++) {
        CP_WAIT2();          // tile kb's group complete (uniform commits)
        __syncthreads();

        const int ti = kb + 3;
        if (ti < nkv) {
            const uint32_t ko = (uint32_t)((ti & 3) * AST * 4);
            const __half* s0 = qkv + kvb0 + (long)ti * 64 * 3072 + 1024;
            const __half* s1 = qkv + kvb1 + (long)ti * 64 * 3072 + 1024;
            CP_ASYNC16(smb + ko + kd0, s0);
            CP_ASYNC16(smb + ko + kd1, s1);
            CP_ASYNC16(vs_b0 + ko + kd0, s0 + 1024);
            CP_ASYNC16(vs_b0 + ko + kd1, s1 + 1024);
        }
        CP_COMMIT();

        const uint32_t* Kc = smu + (kb & 3) * AST;
        const uint32_t vrb = vs_b0 + (uint32_t)((kb & 3) * AST * 4);

        // ---- S = Q @ K^T ----
        float cS[8][4];
#pragma unroll
        for (int nj = 0; nj < 8; nj++)
#pragma unroll
            for (int e = 0; e < 4; e++) cS[nj][e] = 0.f;

#pragma unroll
        for (int ks = 0; ks < 4; ks++) {
#pragma unroll
            for (int nj = 0; nj < 8; nj++) {
                uint32_t bb[2];
                int base = (nj * 8 + gid) * TPW + ks * 8 + tig;
                bb[0] = Kc[base];
                bb[1] = Kc[base + 4];
                mma_f16(cS[nj], qa[ks], bb);
            }
        }

        if (kb >= 2 * qb) {  // causal diagonal tiles
            int rA = qb * 128 + r0 + gid;
            int rB = rA + 8;
#pragma unroll
            for (int nj = 0; nj < 8; nj++) {
                int col = kb * 64 + nj * 8 + 2 * tig;
                if (col     > rA) cS[nj][0] = -3.0e38f;
                if (col + 1 > rA) cS[nj][1] = -3.0e38f;
                if (col     > rB) cS[nj][2] = -3.0e38f;
                if (col + 1 > rB) cS[nj][3] = -3.0e38f;
            }
        }

        // ---- fixed-max softmax: p = exp(s - 8) ----
#pragma unroll
        for (int nj = 0; nj < 8; nj++) {
            cS[nj][0] = __expf(cS[nj][0] - 8.0f); lp0 += cS[nj][0];
            cS[nj][1] = __expf(cS[nj][1] - 8.0f); lp0 += cS[nj][1];
            cS[nj][2] = __expf(cS[nj][2] - 8.0f); lp1 += cS[nj][2];
            cS[nj][3] = __expf(cS[nj][3] - 8.0f); lp1 += cS[nj][3];
        }

        // ---- store P (fp16); warp-private rows ----
#pragma unroll
        for (int nj = 0; nj < 8; nj++) {
            Ps[(r0 + gid) * TPW + nj * 4 + tig]     = f2h2(cS[nj][0], cS[nj][1]);
            Ps[(r0 + gid + 8) * TPW + nj * 4 + tig] = f2h2(cS[nj][2], cS[nj][3]);
        }
        __syncwarp();

        // ---- O += P @ V (V frags via ldmatrix.x2.trans) ----
#pragma unroll
        for (int ks = 0; ks < 4; ks++) {
            uint32_t pa[4];
            int abase = (r0 + gid) * TPW + ks * 8 + tig;
            pa[0] = Ps[abase];
            pa[1] = Ps[abase + 8 * TPW];
            pa[2] = Ps[abase + 4];
            pa[3] = Ps[abase + 8 * TPW + 4];
            const uint32_t vrow = vrb + (uint32_t)((ks * 16 + (lane & 15)) * 144);
#pragma unroll
            for (int nj = 0; nj < 8; nj++) {
                uint32_t bb0, bb1;
                asm volatile(
                    "ldmatrix.sync.aligned.m8n8.x2.trans.shared.b16 {%0,%1}, [%2];"
                    : "=r"(bb0), "=r"(bb1) : "r"(vrow + nj * 16));
                uint32_t bb[2] = {bb0, bb1};
                mma_f16(cO[nj], pa, bb);
            }
        }
    }

    // ---- final row-sum reduction + epilogue (fp16 y) ----
    lp0 += __shfl_xor_sync(0xffffffffu, lp0, 1);
    lp0 += __shfl_xor_sync(0xffffffffu, lp0, 2);
    lp1 += __shfl_xor_sync(0xffffffffu, lp1, 1);
    lp1 += __shfl_xor_sync(0xffffffffu, lp1, 2);
    float inv0 = 1.0f / lp0, inv1 = 1.0f / lp1;
    long rowA = (long)(b * TT + qb * 128 + r0 + gid) * 1024 + h * 64;
    long rowB = rowA + 8 * 1024;
#pragma unroll
    for (int nj = 0; nj < 8; nj++) {
        int col = nj * 8 + 2 * tig;
        *(uint32_t*)(y + rowA + col) = f2h2(cO[nj][0] * inv0, cO[nj][1] * inv0);
        *(uint32_t*)(y + rowB + col) = f2h2(cO[nj][2] * inv1, cO[nj][3] * inv1);
    }
}

// ---------------------------------------------------------------------------
extern "C" void kernel_launch(void* const* d_in, const int* in_sizes, int n_in,
                              void* d_out, int out_size) {
    const float* x      = (const float*)d_in[0];
    const float* cosb   = (const float*)d_in[1];
    const float* sinb   = (const float*)d_in[2];
    const float* W_attn = (const float*)d_in[3];
    const float* b_attn = (const float*)d_in[4];
    const float* W_proj = (const float*)d_in[5];
    const float* b_proj = (const float*)d_in[6];
    float* out = (float*)d_out;

    __half *x16, *qkv16, *y16, *wta, *wtp;
    cudaGetSymbolAddress((void**)&x16, g_x16);
    cudaGetSymbolAddress((void**)&qkv16, g_qkv16);
    cudaGetSymbolAddress((void**)&y16, g_y16);
    cudaGetSymbolAddress((void**)&wta, g_wta16);
    cudaGetSymbolAddress((void**)&wtp, g_wtp16);

    // 0) converts: x -> fp16; weights -> fp16 [N][K]
    convert_x<<<4096, 256>>>(x, x16);
    transpose_w_h<<<dim3(96, 32), 256>>>(W_attn, wta, 1024, 3072);
    transpose_w_h<<<dim3(32, 32), 256>>>(W_proj, wtp, 1024, 1024);

    // 1) QKV GEMM (fp16, 4-stage cp.async): -> g_qkv16
    cudaFuncSetAttribute(h16_gemm_bias, cudaFuncAttributeMaxDynamicSharedMemorySize, GEMM_SMEM);
    h16_gemm_bias<<<dim3(3072 / 128, 4096 / 128), 256, GEMM_SMEM>>>(
        x16, wta, b_attn, qkv16, 4096, 3072, 1024, 1);

    // 2) per-head RMSNorm + RoPE on q,k (fp16 in place)
    norm_rope16_kernel<<<2 * TT, 256>>>(qkv16, cosb, sinb);

    // 3) causal flash attention (fp16, 4-stage cp.async KV, fixed-max softmax)
    cudaFuncSetAttribute(attn_h16_kernel, cudaFuncAttributeMaxDynamicSharedMemorySize, ATT_SMEM);
    attn_h16_kernel<<<dim3(TT / 128, 16, 2), 256, ATT_SMEM>>>(qkv16, y16);

    // 4) output projection (fp16, 4-stage cp.async): -> fp32 out
    h16_gemm_bias<<<dim3(1024 / 128, 4096 / 128), 256, GEMM_SMEM>>>(
        y16, wtp, b_proj, out, 4096, 1024, 1024, 0);
}

// round 15
// speedup vs baseline: 2.2677x; 1.0396x over previous
#include <cuda_runtime.h>
#include <cuda_fp16.h>
#include <cstdint>

// Problem constants: B=2, T=2048, C=1024, H=16, D=64
#define TT 2048

// Scratch (allocation-free rule: __device__ globals)
__device__ __half g_x16[2 * 2048 * 1024];        // x fp16
__device__ __half g_qkv16[2 * 2048 * 3 * 1024];  // [B,T,3,H,D] fp16
__device__ __half g_y16[2 * 2048 * 1024];        // [B,T,H,D] fp16
__device__ __half g_wta16[3072 * 1024];          // W_attn^T fp16 [N][K]
__device__ __half g_wtp16[1024 * 1024];          // W_proj^T fp16 [N][K]

__device__ __forceinline__ uint32_t f2h2(float lo, float hi) {
    __half2 h = __floats2half2_rn(lo, hi);
    return *reinterpret_cast<uint32_t*>(&h);
}

__device__ __forceinline__ void mma_f16(float* c, const uint32_t* a, const uint32_t* b) {
    asm volatile(
        "mma.sync.aligned.m16n8k16.row.col.f32.f16.f16.f32 "
        "{%0,%1,%2,%3}, {%4,%5,%6,%7}, {%8,%9}, {%0,%1,%2,%3};\n"
        : "+f"(c[0]), "+f"(c[1]), "+f"(c[2]), "+f"(c[3])
        : "r"(a[0]), "r"(a[1]), "r"(a[2]), "r"(a[3]), "r"(b[0]), "r"(b[1]));
}

#define CP_ASYNC16(dst_u32, src) \
    asm volatile("cp.async.cg.shared.global [%0], [%1], 16;\n" :: "r"(dst_u32), "l"(src))
#define CP_COMMIT() asm volatile("cp.async.commit_group;\n" ::: "memory")
#define CP_WAIT2()  asm volatile("cp.async.wait_group 2;\n" ::: "memory")

// ---------------------------------------------------------------------------
// x fp32 -> fp16
// ---------------------------------------------------------------------------
__global__ __launch_bounds__(256)
void convert_x(const float* __restrict__ x, __half* __restrict__ x16) {
    const long i = ((long)blockIdx.x * 256 + threadIdx.x) * 4;
    float4 v = *(const float4*)(x + i);
    uint2 u;
    u.x = f2h2(v.x, v.y);
    u.y = f2h2(v.z, v.w);
    *(uint2*)(x16 + i) = u;
}

// ---------------------------------------------------------------------------
// Weight transpose + fp16 convert: Wt16[n][k] = (half)W[k][n]
// ---------------------------------------------------------------------------
__global__ __launch_bounds__(256)
void transpose_w_h(const float* __restrict__ W, __half* __restrict__ Wt, int K, int N) {
    __shared__ float t[32][33];
    const int n0 = blockIdx.x * 32, k0 = blockIdx.y * 32;
    const int x = threadIdx.x & 31, y = threadIdx.x >> 5;
#pragma unroll
    for (int i = 0; i < 4; i++)
        t[y + 8 * i][x] = W[(long)(k0 + y + 8 * i) * N + n0 + x];
    __syncthreads();
#pragma unroll
    for (int i = 0; i < 4; i++)
        Wt[(long)(n0 + y + 8 * i) * K + k0 + x] = __float2half_rn(t[x][y + 8 * i]);
}

// ---------------------------------------------------------------------------
// FP16 GEMM with bias, cp.async 4-stage pipeline, one-ahead B frags.
// 256 thr, 8 warps (4x2), 128x128 tile, BK=32.
// ---------------------------------------------------------------------------
#define AP 20
#define GST 2560
#define GEMM_SMEM (8 * GST * 4)

__global__ __launch_bounds__(256, 2)
void h16_gemm_bias(const __half* __restrict__ A, const __half* __restrict__ Bt,
                   const float* __restrict__ bias, void* __restrict__ CoutV,
                   int M, int N, int K, int out16) {
    extern __shared__ uint32_t gsm[];
    const uint32_t smb = (uint32_t)__cvta_generic_to_shared(gsm);

    const int tid = threadIdx.x;
    const int lane = tid & 31;
    const int warp = tid >> 5;
    const int gid = lane >> 2;
    const int tig = lane & 3;
    const int wm = warp >> 1;
    const int wn = warp & 1;
    const int m0w = wm * 32;
    const int n0w = wn * 64;
    const int br = blockIdx.y * 128;
    const int bc = blockIdx.x * 128;

    const int r0c = tid >> 2, o0c = tid & 3;
    const int r1c = (tid + 256) >> 2, o1c = tid & 3;
    const uint32_t ad0 = (uint32_t)(r0c * 80 + o0c * 16);
    const uint32_t ad1 = (uint32_t)(r1c * 80 + o1c * 16);

    const __half* A0 = A + (long)(br + r0c) * K + o0c * 8;
    const __half* A1 = A + (long)(br + r1c) * K + o1c * 8;
    const __half* B0 = Bt + (long)(bc + r0c) * K + o0c * 8;
    const __half* B1 = Bt + (long)(bc + r1c) * K + o1c * 8;

    float c[2][8][4];
#pragma unroll
    for (int mi = 0; mi < 2; mi++)
#pragma unroll
        for (int nj = 0; nj < 8; nj++)
#pragma unroll
            for (int e = 0; e < 4; e++) c[mi][nj][e] = 0.f;

    const int nch = K >> 5;
#pragma unroll
    for (int p = 0; p < 3; p++) {
        const uint32_t as_s = smb + (uint32_t)(p * GST * 4);
        const uint32_t bs_s = smb + (uint32_t)((4 + p) * GST * 4);
        CP_ASYNC16(as_s + ad0, A0 + p * 32);
        CP_ASYNC16(as_s + ad1, A1 + p * 32);
        CP_ASYNC16(bs_s + ad0, B0 + p * 32);
        CP_ASYNC16(bs_s + ad1, B1 + p * 32);
        CP_COMMIT();
    }

    for (int ch = 0; ch < nch; ch++) {
        CP_WAIT2();
        __syncthreads();

        const int ci = ch + 3;
        if (ci < nch) {
            const uint32_t as_s = smb + (uint32_t)((ci & 3) * GST * 4);
            const uint32_t bs_s = smb + (uint32_t)((4 + (ci & 3)) * GST * 4);
            CP_ASYNC16(as_s + ad0, A0 + ci * 32);
            CP_ASYNC16(as_s + ad1, A1 + ci * 32);
            CP_ASYNC16(bs_s + ad0, B0 + ci * 32);
            CP_ASYNC16(bs_s + ad1, B1 + ci * 32);
        }
        CP_COMMIT();

        const uint32_t* As = gsm + (ch & 3) * GST;
        const uint32_t* Bs = gsm + (4 + (ch & 3)) * GST;
#pragma unroll
        for (int ks = 0; ks < 2; ks++) {
            uint32_t a[2][4];
#pragma unroll
            for (int mi = 0; mi < 2; mi++) {
                int base = (m0w + mi * 16 + gid) * AP + ks * 8 + tig;
                a[mi][0] = As[base];
                a[mi][1] = As[base + 8 * AP];
                a[mi][2] = As[base + 4];
                a[mi][3] = As[base + 8 * AP + 4];
            }
            // one-ahead B fragment pipeline (2 live regs, interleaves LDS/mma)
            uint32_t bc2[2], bn2[2];
            {
                int b0 = (n0w + gid) * AP + ks * 8 + tig;
                bc2[0] = Bs[b0];
                bc2[1] = Bs[b0 + 4];
            }
#pragma unroll
            for (int nj = 0; nj < 8; nj++) {
                if (nj < 7) {
                    int bn = (n0w + (nj + 1) * 8 + gid) * AP + ks * 8 + tig;
                    bn2[0] = Bs[bn];
                    bn2[1] = Bs[bn + 4];
                }
                mma_f16(c[0][nj], a[0], bc2);
                mma_f16(c[1][nj], a[1], bc2);
                bc2[0] = bn2[0];
                bc2[1] = bn2[1];
            }
        }
    }

    // epilogue
#pragma unroll
    for (int mi = 0; mi < 2; mi++) {
        int row = br + m0w + mi * 16 + gid;
#pragma unroll
        for (int nj = 0; nj < 8; nj++) {
            int col = bc + n0w + nj * 8 + tig * 2;
            float2 bb = *(const float2*)(bias + col);
            float o00 = c[mi][nj][0] + bb.x, o01 = c[mi][nj][1] + bb.y;
            float o10 = c[mi][nj][2] + bb.x, o11 = c[mi][nj][3] + bb.y;
            if (out16) {
                __half* Ch = (__half*)CoutV;
                *(uint32_t*)(Ch + (long)row * N + col) = f2h2(o00, o01);
                *(uint32_t*)(Ch + (long)(row + 8) * N + col) = f2h2(o10, o11);
            } else {
                float* Cf = (float*)CoutV;
                *(float2*)(Cf + (long)row * N + col) = make_float2(o00, o01);
                *(float2*)(Cf + (long)(row + 8) * N + col) = make_float2(o10, o11);
            }
        }
    }
}

// ---------------------------------------------------------------------------
// Fused per-head RMSNorm + RoPE on q,k of g_qkv16 (fp16 in/out, fp32 math).
// ---------------------------------------------------------------------------
__global__ __launch_bounds__(256)
void norm_rope16_kernel(__half* __restrict__ qkv,
                        const float* __restrict__ cosb,
                        const float* __restrict__ sinb) {
    __shared__ float qn[1024];
    __shared__ float kn[1024];
    const int bt = blockIdx.x;
    const int t = bt & (TT - 1);
    const int tid = threadIdx.x;
    __half* qrow = qkv + (long)bt * 3072;
    __half* krow = qrow + 1024;

    const int i = tid * 4;
    uint2 qu = *(const uint2*)(qrow + i);
    uint2 ku = *(const uint2*)(krow + i);
    float2 q01 = __half22float2(*(__half2*)&qu.x);
    float2 q23 = __half22float2(*(__half2*)&qu.y);
    float2 k01 = __half22float2(*(__half2*)&ku.x);
    float2 k23 = __half22float2(*(__half2*)&ku.y);

    float qs = q01.x * q01.x + q01.y * q01.y + q23.x * q23.x + q23.y * q23.y;
    float ks = k01.x * k01.x + k01.y * k01.y + k23.x * k23.x + k23.y * k23.y;
#pragma unroll
    for (int o = 8; o > 0; o >>= 1) {
        qs += __shfl_xor_sync(0xffffffffu, qs, o);
        ks += __shfl_xor_sync(0xffffffffu, ks, o);
    }
    const float qsc = rsqrtf(qs * (1.f / 64.f) + 1.1920929e-07f);
    const float ksc = rsqrtf(ks * (1.f / 64.f) + 1.1920929e-07f);
    qn[i + 0] = q01.x * qsc; qn[i + 1] = q01.y * qsc;
    qn[i + 2] = q23.x * qsc; qn[i + 3] = q23.y * qsc;
    kn[i + 0] = k01.x * ksc; kn[i + 1] = k01.y * ksc;
    kn[i + 2] = k23.x * ksc; kn[i + 3] = k23.y * ksc;
    __syncthreads();

    const int d = i & 63;
    const int base = i - d;
    float4 cv = *(const float4*)(cosb + t * 64 + d);
    float4 sv = *(const float4*)(sinb + t * 64 + d);
    float rq[4], rk[4];
    if (d < 32) {
#pragma unroll
        for (int j = 0; j < 4; j++) {
            rq[j] = -qn[base + d + 32 + j];
            rk[j] = -kn[base + d + 32 + j];
        }
    } else {
#pragma unroll
        for (int j = 0; j < 4; j++) {
            rq[j] = qn[base + d - 32 + j];
            rk[j] = kn[base + d - 32 + j];
        }
    }
    float cc[4] = {cv.x, cv.y, cv.z, cv.w};
    float ss[4] = {sv.x, sv.y, sv.z, sv.w};
    float oq[4], ok[4];
#pragma unroll
    for (int j = 0; j < 4; j++) {
        oq[j] = qn[i + j] * cc[j] + rq[j] * ss[j];
        ok[j] = kn[i + j] * cc[j] + rk[j] * ss[j];
    }
    uint2 qo, ko;
    qo.x = f2h2(oq[0], oq[1]); qo.y = f2h2(oq[2], oq[3]);
    ko.x = f2h2(ok[0], ok[1]); ko.y = f2h2(ok[2], ok[3]);
    *(uint2*)(qrow + i) = qo;
    *(uint2*)(krow + i) = ko;
}

// ---------------------------------------------------------------------------
// FP16 flash attention: fixed-max softmax, 4-stage cp.async K/V, and
// P kept entirely in registers (S C-frags repack directly into PV A-frags —
// layouts match element-for-element; no smem round trip, no syncwarp).
// ---------------------------------------------------------------------------
#define TPW 36
#define AST 2304
#define ATT_SMEM ((8 * AST + 4608) * 4)

__global__ __launch_bounds__(256, 2)
void attn_h16_kernel(const __half* __restrict__ qkv, __half* __restrict__ y) {
    extern __shared__ uint32_t smu[];
    uint32_t* Ps = smu + 8 * AST;         // Q staging only
    const uint32_t smb = (uint32_t)__cvta_generic_to_shared(smu);
    const uint32_t vs_b0 = smb + 4 * AST * 4;

    const int qb = (int)(gridDim.x - 1) - (int)blockIdx.x;  // heavy CTAs first
    const int h = blockIdx.y, b = blockIdx.z;
    const int tid = threadIdx.x;
    const int lane = tid & 31, warp = tid >> 5;
    const int gid = lane >> 2, tig = lane & 3;
    const int r0 = warp * 16;

    const int kc0 = tid * 2, kc1 = tid * 2 + 1;
    const int krow0 = kc0 >> 3, ko0 = kc0 & 7;
    const int krow1 = kc1 >> 3, ko1 = kc1 & 7;
    const long kvb0 = ((long)(b * TT + krow0) * 3) * 1024 + h * 64 + ko0 * 8;
    const long kvb1 = ((long)(b * TT + krow1) * 3) * 1024 + h * 64 + ko1 * 8;
    const uint32_t kd0 = (uint32_t)(krow0 * 144 + ko0 * 16);
    const uint32_t kd1 = (uint32_t)(krow1 * 144 + ko1 * 16);

    const int nkv = 2 * (qb + 1);

#pragma unroll
    for (int p = 0; p < 3; p++) {
        if (p < nkv) {
            const uint32_t ko = (uint32_t)(p * AST * 4);
            const __half* s0 = qkv + kvb0 + (long)p * 64 * 3072 + 1024;
            const __half* s1 = qkv + kvb1 + (long)p * 64 * 3072 + 1024;
            CP_ASYNC16(smb + ko + kd0, s0);
            CP_ASYNC16(smb + ko + kd1, s1);
            CP_ASYNC16(vs_b0 + ko + kd0, s0 + 1024);
            CP_ASYNC16(vs_b0 + ko + kd1, s1 + 1024);
        }
        CP_COMMIT();
    }

    // ---- stage Q (x 1/8 exact) into Ps; load A-fragments ----
    {
        const __half2 qscale = __floats2half2_rn(0.125f, 0.125f);
        const int row = tid >> 1;
        const int dh = (tid & 1) * 32;
        const uint4* src = (const uint4*)(qkv + ((long)(b * TT + qb * 128 + row) * 3) * 1024 + h * 64 + dh);
#pragma unroll
        for (int j = 0; j < 4; j++) {
            uint4 u = src[j];
            __half2* hp = (__half2*)&u;
            hp[0] = __hmul2(hp[0], qscale);
            hp[1] = __hmul2(hp[1], qscale);
            hp[2] = __hmul2(hp[2], qscale);
            hp[3] = __hmul2(hp[3], qscale);
            *(uint4*)&Ps[row * TPW + (tid & 1) * 16 + j * 4] = u;
        }
    }
    __syncthreads();
    uint32_t qa[4][4];
#pragma unroll
    for (int ks = 0; ks < 4; ks++) {
        int base = (r0 + gid) * TPW + ks * 8 + tig;
        qa[ks][0] = Ps[base];
        qa[ks][1] = Ps[base + 8 * TPW];
        qa[ks][2] = Ps[base + 4];
        qa[ks][3] = Ps[base + 8 * TPW + 4];
    }

    float cO[8][4];
#pragma unroll
    for (int nj = 0; nj < 8; nj++)
#pragma unroll
        for (int e = 0; e < 4; e++) cO[nj][e] = 0.f;
    float lp0 = 0.f, lp1 = 0.f;

    for (int kb = 0; kb < nkv; kb++) {
        CP_WAIT2();
        __syncthreads();

        const int ti = kb + 3;
        if (ti < nkv) {
            const uint32_t ko = (uint32_t)((ti & 3) * AST * 4);
            const __half* s0 = qkv + kvb0 + (long)ti * 64 * 3072 + 1024;
            const __half* s1 = qkv + kvb1 + (long)ti * 64 * 3072 + 1024;
            CP_ASYNC16(smb + ko + kd0, s0);
            CP_ASYNC16(smb + ko + kd1, s1);
            CP_ASYNC16(vs_b0 + ko + kd0, s0 + 1024);
            CP_ASYNC16(vs_b0 + ko + kd1, s1 + 1024);
        }
        CP_COMMIT();

        const uint32_t* Kc = smu + (kb & 3) * AST;
        const uint32_t vrb = vs_b0 + (uint32_t)((kb & 3) * AST * 4);

        // ---- S = Q @ K^T (one-ahead B frags) ----
        float cS[8][4];
#pragma unroll
        for (int nj = 0; nj < 8; nj++)
#pragma unroll
            for (int e = 0; e < 4; e++) cS[nj][e] = 0.f;

#pragma unroll
        for (int ks = 0; ks < 4; ks++) {
            uint32_t bc2[2], bn2[2];
            {
                int b0 = gid * TPW + ks * 8 + tig;
                bc2[0] = Kc[b0];
                bc2[1] = Kc[b0 + 4];
            }
#pragma unroll
            for (int nj = 0; nj < 8; nj++) {
                if (nj < 7) {
                    int bn = ((nj + 1) * 8 + gid) * TPW + ks * 8 + tig;
                    bn2[0] = Kc[bn];
                    bn2[1] = Kc[bn + 4];
                }
                mma_f16(cS[nj], qa[ks], bc2);
                bc2[0] = bn2[0];
                bc2[1] = bn2[1];
            }
        }

        if (kb >= 2 * qb) {  // causal diagonal tiles
            int rA = qb * 128 + r0 + gid;
            int rB = rA + 8;
#pragma unroll
            for (int nj = 0; nj < 8; nj++) {
                int col = kb * 64 + nj * 8 + 2 * tig;
                if (col     > rA) cS[nj][0] = -3.0e38f;
                if (col + 1 > rA) cS[nj][1] = -3.0e38f;
                if (col     > rB) cS[nj][2] = -3.0e38f;
                if (col + 1 > rB) cS[nj][3] = -3.0e38f;
            }
        }

        // ---- fixed-max softmax: p = exp(s - 8) ----
#pragma unroll
        for (int nj = 0; nj < 8; nj++) {
            cS[nj][0] = __expf(cS[nj][0] - 8.0f); lp0 += cS[nj][0];
            cS[nj][1] = __expf(cS[nj][1] - 8.0f); lp0 += cS[nj][1];
            cS[nj][2] = __expf(cS[nj][2] - 8.0f); lp1 += cS[nj][2];
            cS[nj][3] = __expf(cS[nj][3] - 8.0f); lp1 += cS[nj][3];
        }

        // ---- pack P: S C-frags -> PV A-frags, entirely in registers ----
        uint32_t pf[4][4];
#pragma unroll
        for (int ks = 0; ks < 4; ks++) {
            pf[ks][0] = f2h2(cS[2 * ks][0],     cS[2 * ks][1]);
            pf[ks][1] = f2h2(cS[2 * ks][2],     cS[2 * ks][3]);
            pf[ks][2] = f2h2(cS[2 * ks + 1][0], cS[2 * ks + 1][1]);
            pf[ks][3] = f2h2(cS[2 * ks + 1][2], cS[2 * ks + 1][3]);
        }

        // ---- O += P @ V (V frags via ldmatrix.x2.trans) ----
#pragma unroll
        for (int ks = 0; ks < 4; ks++) {
            const uint32_t vrow = vrb + (uint32_t)((ks * 16 + (lane & 15)) * 144);
#pragma unroll
            for (int nj = 0; nj < 8; nj++) {
                uint32_t bb0, bb1;
                asm volatile(
                    "ldmatrix.sync.aligned.m8n8.x2.trans.shared.b16 {%0,%1}, [%2];"
                    : "=r"(bb0), "=r"(bb1) : "r"(vrow + nj * 16));
                uint32_t bb[2] = {bb0, bb1};
                mma_f16(cO[nj], pf[ks], bb);
            }
        }
    }

    // ---- final row-sum reduction + epilogue (fp16 y) ----
    lp0 += __shfl_xor_sync(0xffffffffu, lp0, 1);
    lp0 += __shfl_xor_sync(0xffffffffu, lp0, 2);
    lp1 += __shfl_xor_sync(0xffffffffu, lp1, 1);
    lp1 += __shfl_xor_sync(0xffffffffu, lp1, 2);
    float inv0 = 1.0f / lp0, inv1 = 1.0f / lp1;
    long rowA = (long)(b * TT + qb * 128 + r0 + gid) * 1024 + h * 64;
    long rowB = rowA + 8 * 1024;
#pragma unroll
    for (int nj = 0; nj < 8; nj++) {
        int col = nj * 8 + 2 * tig;
        *(uint32_t*)(y + rowA + col) = f2h2(cO[nj][0] * inv0, cO[nj][1] * inv0);
        *(uint32_t*)(y + rowB + col) = f2h2(cO[nj][2] * inv1, cO[nj][3] * inv1);
    }
}

// ---------------------------------------------------------------------------
extern "C" void kernel_launch(void* const* d_in, const int* in_sizes, int n_in,
                              void* d_out, int out_size) {
    const float* x      = (const float*)d_in[0];
    const float* cosb   = (const float*)d_in[1];
    const float* sinb   = (const float*)d_in[2];
    const float* W_attn = (const float*)d_in[3];
    const float* b_attn = (const float*)d_in[4];
    const float* W_proj = (const float*)d_in[5];
    const float* b_proj = (const float*)d_in[6];
    float* out = (float*)d_out;

    __half *x16, *qkv16, *y16, *wta, *wtp;
    cudaGetSymbolAddress((void**)&x16, g_x16);
    cudaGetSymbolAddress((void**)&qkv16, g_qkv16);
    cudaGetSymbolAddress((void**)&y16, g_y16);
    cudaGetSymbolAddress((void**)&wta, g_wta16);
    cudaGetSymbolAddress((void**)&wtp, g_wtp16);

    // 0) converts: x -> fp16; weights -> fp16 [N][K]
    convert_x<<<4096, 256>>>(x, x16);
    transpose_w_h<<<dim3(96, 32), 256>>>(W_attn, wta, 1024, 3072);
    transpose_w_h<<<dim3(32, 32), 256>>>(W_proj, wtp, 1024, 1024);

    // 1) QKV GEMM (fp16, 4-stage cp.async): -> g_qkv16
    cudaFuncSetAttribute(h16_gemm_bias, cudaFuncAttributeMaxDynamicSharedMemorySize, GEMM_SMEM);
    h16_gemm_bias<<<dim3(3072 / 128, 4096 / 128), 256, GEMM_SMEM>>>(
        x16, wta, b_attn, qkv16, 4096, 3072, 1024, 1);

    // 2) per-head RMSNorm + RoPE on q,k (fp16 in place)
    norm_rope16_kernel<<<2 * TT, 256>>>(qkv16, cosb, sinb);

    // 3) causal flash attention (fp16, register-resident P)
    cudaFuncSetAttribute(attn_h16_kernel, cudaFuncAttributeMaxDynamicSharedMemorySize, ATT_SMEM);
    attn_h16_kernel<<<dim3(TT / 128, 16, 2), 256, ATT_SMEM>>>(qkv16, y16);

    // 4) output projection (fp16, 4-stage cp.async): -> fp32 out
    h16_gemm_bias<<<dim3(1024 / 128, 4096 / 128), 256, GEMM_SMEM>>>(
        y16, wtp, b_proj, out, 4096, 1024, 1024, 0);
}

// round 16
// speedup vs baseline: 2.3409x; 1.0322x over previous
#include <cuda_runtime.h>
#include <cuda_fp16.h>
#include <cstdint>

// Problem constants: B=2, T=2048, C=1024, H=16, D=64
#define TT 2048

// Scratch (allocation-free rule: __device__ globals)
__device__ __half g_x16[2 * 2048 * 1024];        // x fp16
__device__ __half g_qkv16[2 * 2048 * 3 * 1024];  // [B,T,3,H,D] fp16 (q,k normed+roped)
__device__ __half g_y16[2 * 2048 * 1024];        // [B,T,H,D] fp16
__device__ __half g_wta16[3072 * 1024];          // W_attn^T fp16 [N][K]
__device__ __half g_wtp16[1024 * 1024];          // W_proj^T fp16 [N][K]

__device__ __forceinline__ uint32_t f2h2(float lo, float hi) {
    __half2 h = __floats2half2_rn(lo, hi);
    return *reinterpret_cast<uint32_t*>(&h);
}

__device__ __forceinline__ void mma_f16(float* c, const uint32_t* a, const uint32_t* b) {
    asm volatile(
        "mma.sync.aligned.m16n8k16.row.col.f32.f16.f16.f32 "
        "{%0,%1,%2,%3}, {%4,%5,%6,%7}, {%8,%9}, {%0,%1,%2,%3};\n"
        : "+f"(c[0]), "+f"(c[1]), "+f"(c[2]), "+f"(c[3])
        : "r"(a[0]), "r"(a[1]), "r"(a[2]), "r"(a[3]), "r"(b[0]), "r"(b[1]));
}

#define CP_ASYNC16(dst_u32, src) \
    asm volatile("cp.async.cg.shared.global [%0], [%1], 16;\n" :: "r"(dst_u32), "l"(src))
#define CP_COMMIT() asm volatile("cp.async.commit_group;\n" ::: "memory")
#define CP_WAIT2()  asm volatile("cp.async.wait_group 2;\n" ::: "memory")

// ---------------------------------------------------------------------------
// Merged prepass: blocks [0,4096) convert x; [4096,7168) transpose W_attn;
// [7168,8192) transpose W_proj.
// ---------------------------------------------------------------------------
__global__ __launch_bounds__(256)
void prepass_kernel(const float* __restrict__ x, __half* __restrict__ x16,
                    const float* __restrict__ Wa, __half* __restrict__ wta,
                    const float* __restrict__ Wp, __half* __restrict__ wtp) {
    __shared__ float t[32][33];
    const int bid = blockIdx.x;
    if (bid < 4096) {
        const long i = ((long)bid * 256 + threadIdx.x) * 4;
        float4 v = *(const float4*)(x + i);
        uint2 u;
        u.x = f2h2(v.x, v.y);
        u.y = f2h2(v.z, v.w);
        *(uint2*)(x16 + i) = u;
        return;
    }
    const float* W;
    __half* Wt;
    int idx, K, N;
    if (bid < 7168) { idx = bid - 4096; W = Wa; Wt = wta; K = 1024; N = 3072;
        ;} else { idx = bid - 7168; W = Wp; Wt = wtp; K = 1024; N = 1024; }
    const int nblk = N / 32;
    const int n0 = (idx % nblk) * 32, k0 = (idx / nblk) * 32;
    const int xx = threadIdx.x & 31, yy = threadIdx.x >> 5;
#pragma unroll
    for (int i = 0; i < 4; i++)
        t[yy + 8 * i][xx] = W[(long)(k0 + yy + 8 * i) * N + n0 + xx];
    __syncthreads();
#pragma unroll
    for (int i = 0; i < 4; i++)
        Wt[(long)(n0 + yy + 8 * i) * K + k0 + xx] = __float2half_rn(t[xx][yy + 8 * i]);
}

// ---------------------------------------------------------------------------
// FP16 GEMM with bias, cp.async 4-stage pipeline, one-ahead B frags.
// mode 0: fp32 out. mode 1: fp16 out, with fused RMSNorm+RoPE on q/k tiles
// (bc < 2048). Row cols within a head are owned by the 4 tig-lanes (16 each)
// -> shfl xor 1,2 gives the exact 64-col sum; RoPE partner d+-32 is nj^4,
// i.e. the SAME thread. 256 thr, 8 warps (4x2), 128x128 tile, BK=32.
// ---------------------------------------------------------------------------
#define AP 20
#define GST 2560
#define GEMM_SMEM (8 * GST * 4)

__global__ __launch_bounds__(256, 2)
void h16_gemm_bias(const __half* __restrict__ A, const __half* __restrict__ Bt,
                   const float* __restrict__ bias, void* __restrict__ CoutV,
                   const float* __restrict__ cosb, const float* __restrict__ sinb,
                   int M, int N, int K, int mode) {
    extern __shared__ uint32_t gsm[];
    const uint32_t smb = (uint32_t)__cvta_generic_to_shared(gsm);

    const int tid = threadIdx.x;
    const int lane = tid & 31;
    const int warp = tid >> 5;
    const int gid = lane >> 2;
    const int tig = lane & 3;
    const int wm = warp >> 1;
    const int wn = warp & 1;
    const int m0w = wm * 32;
    const int n0w = wn * 64;
    const int br = blockIdx.y * 128;
    const int bc = blockIdx.x * 128;

    const int r0c = tid >> 2, o0c = tid & 3;
    const int r1c = (tid + 256) >> 2, o1c = tid & 3;
    const uint32_t ad0 = (uint32_t)(r0c * 80 + o0c * 16);
    const uint32_t ad1 = (uint32_t)(r1c * 80 + o1c * 16);

    const __half* A0 = A + (long)(br + r0c) * K + o0c * 8;
    const __half* A1 = A + (long)(br + r1c) * K + o1c * 8;
    const __half* B0 = Bt + (long)(bc + r0c) * K + o0c * 8;
    const __half* B1 = Bt + (long)(bc + r1c) * K + o1c * 8;

    float c[2][8][4];
#pragma unroll
    for (int mi = 0; mi < 2; mi++)
#pragma unroll
        for (int nj = 0; nj < 8; nj++)
#pragma unroll
            for (int e = 0; e < 4; e++) c[mi][nj][e] = 0.f;

    const int nch = K >> 5;
#pragma unroll
    for (int p = 0; p < 3; p++) {
        const uint32_t as_s = smb + (uint32_t)(p * GST * 4);
        const uint32_t bs_s = smb + (uint32_t)((4 + p) * GST * 4);
        CP_ASYNC16(as_s + ad0, A0 + p * 32);
        CP_ASYNC16(as_s + ad1, A1 + p * 32);
        CP_ASYNC16(bs_s + ad0, B0 + p * 32);
        CP_ASYNC16(bs_s + ad1, B1 + p * 32);
        CP_COMMIT();
    }

    for (int ch = 0; ch < nch; ch++) {
        CP_WAIT2();
        __syncthreads();

        const int ci = ch + 3;
        if (ci < nch) {
            const uint32_t as_s = smb + (uint32_t)((ci & 3) * GST * 4);
            const uint32_t bs_s = smb + (uint32_t)((4 + (ci & 3)) * GST * 4);
            CP_ASYNC16(as_s + ad0, A0 + ci * 32);
            CP_ASYNC16(as_s + ad1, A1 + ci * 32);
            CP_ASYNC16(bs_s + ad0, B0 + ci * 32);
            CP_ASYNC16(bs_s + ad1, B1 + ci * 32);
        }
        CP_COMMIT();

        const uint32_t* As = gsm + (ch & 3) * GST;
        const uint32_t* Bs = gsm + (4 + (ch & 3)) * GST;
#pragma unroll
        for (int ks = 0; ks < 2; ks++) {
            uint32_t a[2][4];
#pragma unroll
            for (int mi = 0; mi < 2; mi++) {
                int base = (m0w + mi * 16 + gid) * AP + ks * 8 + tig;
                a[mi][0] = As[base];
                a[mi][1] = As[base + 8 * AP];
                a[mi][2] = As[base + 4];
                a[mi][3] = As[base + 8 * AP + 4];
            }
            uint32_t bc2[2], bn2[2];
            {
                int b0 = (n0w + gid) * AP + ks * 8 + tig;
                bc2[0] = Bs[b0];
                bc2[1] = Bs[b0 + 4];
            }
#pragma unroll
            for (int nj = 0; nj < 8; nj++) {
                if (nj < 7) {
                    int bn = (n0w + (nj + 1) * 8 + gid) * AP + ks * 8 + tig;
                    bn2[0] = Bs[bn];
                    bn2[1] = Bs[bn + 4];
                }
                mma_f16(c[0][nj], a[0], bc2);
                mma_f16(c[1][nj], a[1], bc2);
                bc2[0] = bn2[0];
                bc2[1] = bn2[1];
            }
        }
    }

    // ---- epilogue ----
    if (mode == 1) {
        __half* Ch = (__half*)CoutV;
        const bool donr = (bc < 2048);   // q/k tiles get RMSNorm+RoPE
#pragma unroll
        for (int mi = 0; mi < 2; mi++) {
#pragma unroll
            for (int hf = 0; hf < 2; hf++) {   // hf=0 -> row, hf=1 -> row+8
                const int row = br + m0w + mi * 16 + gid + hf * 8;
                float o[8][2];
#pragma unroll
                for (int nj = 0; nj < 8; nj++) {
                    int col = bc + n0w + nj * 8 + tig * 2;
                    float2 bb = *(const float2*)(bias + col);
                    o[nj][0] = c[mi][nj][2 * hf + 0] + bb.x;
                    o[nj][1] = c[mi][nj][2 * hf + 1] + bb.y;
                }
                if (donr) {
                    float ssum = 0.f;
#pragma unroll
                    for (int nj = 0; nj < 8; nj++)
                        ssum += o[nj][0] * o[nj][0] + o[nj][1] * o[nj][1];
                    ssum += __shfl_xor_sync(0xffffffffu, ssum, 1);
                    ssum += __shfl_xor_sync(0xffffffffu, ssum, 2);
                    const float rn = rsqrtf(ssum * (1.f / 64.f) + 1.1920929e-07f);
                    float nv[8][2];
#pragma unroll
                    for (int nj = 0; nj < 8; nj++) {
                        nv[nj][0] = o[nj][0] * rn;
                        nv[nj][1] = o[nj][1] * rn;
                    }
                    const int t = row & (TT - 1);
#pragma unroll
                    for (int nj = 0; nj < 8; nj++) {
                        int d = nj * 8 + tig * 2;
                        float2 cv = *(const float2*)(cosb + t * 64 + d);
                        float2 sv = *(const float2*)(sinb + t * 64 + d);
                        float rr0 = (nj < 4) ? -nv[nj + 4][0] : nv[nj - 4][0];
                        float rr1 = (nj < 4) ? -nv[nj + 4][1] : nv[nj - 4][1];
                        o[nj][0] = nv[nj][0] * cv.x + rr0 * sv.x;
                        o[nj][1] = nv[nj][1] * cv.y + rr1 * sv.y;
                    }
                }
#pragma unroll
                for (int nj = 0; nj < 8; nj++) {
                    int col = bc + n0w + nj * 8 + tig * 2;
                    *(uint32_t*)(Ch + (long)row * N + col) = f2h2(o[nj][0], o[nj][1]);
                }
            }
        }
    } else {
        float* Cf = (float*)CoutV;
#pragma unroll
        for (int mi = 0; mi < 2; mi++) {
            int row = br + m0w + mi * 16 + gid;
#pragma unroll
            for (int nj = 0; nj < 8; nj++) {
                int col = bc + n0w + nj * 8 + tig * 2;
                float2 bb = *(const float2*)(bias + col);
                *(float2*)(Cf + (long)row * N + col) =
                    make_float2(c[mi][nj][0] + bb.x, c[mi][nj][1] + bb.y);
                *(float2*)(Cf + (long)(row + 8) * N + col) =
                    make_float2(c[mi][nj][2] + bb.x, c[mi][nj][3] + bb.y);
            }
        }
    }
}

// ---------------------------------------------------------------------------
// FP16 flash attention: fixed-max softmax, 4-stage cp.async K/V,
// register-resident P (round-15 best, unchanged).
// ---------------------------------------------------------------------------
#define TPW 36
#define AST 2304
#define ATT_SMEM ((8 * AST + 4608) * 4)

__global__ __launch_bounds__(256, 2)
void attn_h16_kernel(const __half* __restrict__ qkv, __half* __restrict__ y) {
    extern __shared__ uint32_t smu[];
    uint32_t* Ps = smu + 8 * AST;
    const uint32_t smb = (uint32_t)__cvta_generic_to_shared(smu);
    const uint32_t vs_b0 = smb + 4 * AST * 4;

    const int qb = (int)(gridDim.x - 1) - (int)blockIdx.x;
    const int h = blockIdx.y, b = blockIdx.z;
    const int tid = threadIdx.x;
    const int lane = tid & 31, warp = tid >> 5;
    const int gid = lane >> 2, tig = lane & 3;
    const int r0 = warp * 16;

    const int kc0 = tid * 2, kc1 = tid * 2 + 1;
    const int krow0 = kc0 >> 3, ko0 = kc0 & 7;
    const int krow1 = kc1 >> 3, ko1 = kc1 & 7;
    const long kvb0 = ((long)(b * TT + krow0) * 3) * 1024 + h * 64 + ko0 * 8;
    const long kvb1 = ((long)(b * TT + krow1) * 3) * 1024 + h * 64 + ko1 * 8;
    const uint32_t kd0 = (uint32_t)(krow0 * 144 + ko0 * 16);
    const uint32_t kd1 = (uint32_t)(krow1 * 144 + ko1 * 16);

    const int nkv = 2 * (qb + 1);

#pragma unroll
    for (int p = 0; p < 3; p++) {
        if (p < nkv) {
            const uint32_t ko = (uint32_t)(p * AST * 4);
            const __half* s0 = qkv + kvb0 + (long)p * 64 * 3072 + 1024;
            const __half* s1 = qkv + kvb1 + (long)p * 64 * 3072 + 1024;
            CP_ASYNC16(smb + ko + kd0, s0);
            CP_ASYNC16(smb + ko + kd1, s1);
            CP_ASYNC16(vs_b0 + ko + kd0, s0 + 1024);
            CP_ASYNC16(vs_b0 + ko + kd1, s1 + 1024);
        }
        CP_COMMIT();
    }

    {
        const __half2 qscale = __floats2half2_rn(0.125f, 0.125f);
        const int row = tid >> 1;
        const int dh = (tid & 1) * 32;
        const uint4* src = (const uint4*)(qkv + ((long)(b * TT + qb * 128 + row) * 3) * 1024 + h * 64 + dh);
#pragma unroll
        for (int j = 0; j < 4; j++) {
            uint4 u = src[j];
            __half2* hp = (__half2*)&u;
            hp[0] = __hmul2(hp[0], qscale);
            hp[1] = __hmul2(hp[1], qscale);
            hp[2] = __hmul2(hp[2], qscale);
            hp[3] = __hmul2(hp[3], qscale);
            *(uint4*)&Ps[row * TPW + (tid & 1) * 16 + j * 4] = u;
        }
    }
    __syncthreads();
    uint32_t qa[4][4];
#pragma unroll
    for (int ks = 0; ks < 4; ks++) {
        int base = (r0 + gid) * TPW + ks * 8 + tig;
        qa[ks][0] = Ps[base];
        qa[ks][1] = Ps[base + 8 * TPW];
        qa[ks][2] = Ps[base + 4];
        qa[ks][3] = Ps[base + 8 * TPW + 4];
    }

    float cO[8][4];
#pragma unroll
    for (int nj = 0; nj < 8; nj++)
#pragma unroll
        for (int e = 0; e < 4; e++) cO[nj][e] = 0.f;
    float lp0 = 0.f, lp1 = 0.f;

    for (int kb = 0; kb < nkv; kb++) {
        CP_WAIT2();
        __syncthreads();

        const int ti = kb + 3;
        if (ti < nkv) {
            const uint32_t ko = (uint32_t)((ti & 3) * AST * 4);
            const __half* s0 = qkv + kvb0 + (long)ti * 64 * 3072 + 1024;
            const __half* s1 = qkv + kvb1 + (long)ti * 64 * 3072 + 1024;
            CP_ASYNC16(smb + ko + kd0, s0);
            CP_ASYNC16(smb + ko + kd1, s1);
            CP_ASYNC16(vs_b0 + ko + kd0, s0 + 1024);
            CP_ASYNC16(vs_b0 + ko + kd1, s1 + 1024);
        }
        CP_COMMIT();

        const uint32_t* Kc = smu + (kb & 3) * AST;
        const uint32_t vrb = vs_b0 + (uint32_t)((kb & 3) * AST * 4);

        float cS[8][4];
#pragma unroll
        for (int nj = 0; nj < 8; nj++)
#pragma unroll
            for (int e = 0; e < 4; e++) cS[nj][e] = 0.f;

#pragma unroll
        for (int ks = 0; ks < 4; ks++) {
            uint32_t bc2[2], bn2[2];
            {
                int b0 = gid * TPW + ks * 8 + tig;
                bc2[0] = Kc[b0];
                bc2[1] = Kc[b0 + 4];
            }
#pragma unroll
            for (int nj = 0; nj < 8; nj++) {
                if (nj < 7) {
                    int bn = ((nj + 1) * 8 + gid) * TPW + ks * 8 + tig;
                    bn2[0] = Kc[bn];
                    bn2[1] = Kc[bn + 4];
                }
                mma_f16(cS[nj], qa[ks], bc2);
                bc2[0] = bn2[0];
                bc2[1] = bn2[1];
            }
        }

        if (kb >= 2 * qb) {
            int rA = qb * 128 + r0 + gid;
            int rB = rA + 8;
#pragma unroll
            for (int nj = 0; nj < 8; nj++) {
                int col = kb * 64 + nj * 8 + 2 * tig;
                if (col     > rA) cS[nj][0] = -3.0e38f;
                if (col + 1 > rA) cS[nj][1] = -3.0e38f;
                if (col     > rB) cS[nj][2] = -3.0e38f;
                if (col + 1 > rB) cS[nj][3] = -3.0e38f;
            }
        }

#pragma unroll
        for (int nj = 0; nj < 8; nj++) {
            cS[nj][0] = __expf(cS[nj][0] - 8.0f); lp0 += cS[nj][0];
            cS[nj][1] = __expf(cS[nj][1] - 8.0f); lp0 += cS[nj][1];
            cS[nj][2] = __expf(cS[nj][2] - 8.0f); lp1 += cS[nj][2];
            cS[nj][3] = __expf(cS[nj][3] - 8.0f); lp1 += cS[nj][3];
        }

        uint32_t pf[4][4];
#pragma unroll
        for (int ks = 0; ks < 4; ks++) {
            pf[ks][0] = f2h2(cS[2 * ks][0],     cS[2 * ks][1]);
            pf[ks][1] = f2h2(cS[2 * ks][2],     cS[2 * ks][3]);
            pf[ks][2] = f2h2(cS[2 * ks + 1][0], cS[2 * ks + 1][1]);
            pf[ks][3] = f2h2(cS[2 * ks + 1][2], cS[2 * ks + 1][3]);
        }

#pragma unroll
        for (int ks = 0; ks < 4; ks++) {
            const uint32_t vrow = vrb + (uint32_t)((ks * 16 + (lane & 15)) * 144);
#pragma unroll
            for (int nj = 0; nj < 8; nj++) {
                uint32_t bb0, bb1;
                asm volatile(
                    "ldmatrix.sync.aligned.m8n8.x2.trans.shared.b16 {%0,%1}, [%2];"
                    : "=r"(bb0), "=r"(bb1) : "r"(vrow + nj * 16));
                uint32_t bb[2] = {bb0, bb1};
                mma_f16(cO[nj], pf[ks], bb);
            }
        }
    }

    lp0 += __shfl_xor_sync(0xffffffffu, lp0, 1);
    lp0 += __shfl_xor_sync(0xffffffffu, lp0, 2);
    lp1 += __shfl_xor_sync(0xffffffffu, lp1, 1);
    lp1 += __shfl_xor_sync(0xffffffffu, lp1, 2);
    float inv0 = 1.0f / lp0, inv1 = 1.0f / lp1;
    long rowA = (long)(b * TT + qb * 128 + r0 + gid) * 1024 + h * 64;
    long rowB = rowA + 8 * 1024;
#pragma unroll
    for (int nj = 0; nj < 8; nj++) {
        int col = nj * 8 + 2 * tig;
        *(uint32_t*)(y + rowA + col) = f2h2(cO[nj][0] * inv0, cO[nj][1] * inv0);
        *(uint32_t*)(y + rowB + col) = f2h2(cO[nj][2] * inv1, cO[nj][3] * inv1);
    }
}

// ---------------------------------------------------------------------------
extern "C" void kernel_launch(void* const* d_in, const int* in_sizes, int n_in,
                              void* d_out, int out_size) {
    const float* x      = (const float*)d_in[0];
    const float* cosb   = (const float*)d_in[1];
    const float* sinb   = (const float*)d_in[2];
    const float* W_attn = (const float*)d_in[3];
    const float* b_attn = (const float*)d_in[4];
    const float* W_proj = (const float*)d_in[5];
    const float* b_proj = (const float*)d_in[6];
    float* out = (float*)d_out;

    __half *x16, *qkv16, *y16, *wta, *wtp;
    cudaGetSymbolAddress((void**)&x16, g_x16);
    cudaGetSymbolAddress((void**)&qkv16, g_qkv16);
    cudaGetSymbolAddress((void**)&y16, g_y16);
    cudaGetSymbolAddress((void**)&wta, g_wta16);
    cudaGetSymbolAddress((void**)&wtp, g_wtp16);

    // 0) merged prepass: x->fp16, both weight transposes
    prepass_kernel<<<8192, 256>>>(x, x16, W_attn, wta, W_proj, wtp);

    // 1) QKV GEMM with fused RMSNorm+RoPE epilogue: -> g_qkv16
    cudaFuncSetAttribute(h16_gemm_bias, cudaFuncAttributeMaxDynamicSharedMemorySize, GEMM_SMEM);
    h16_gemm_bias<<<dim3(3072 / 128, 4096 / 128), 256, GEMM_SMEM>>>(
        x16, wta, b_attn, qkv16, cosb, sinb, 4096, 3072, 1024, 1);

    // 2) causal flash attention (fp16, register-resident P)
    cudaFuncSetAttribute(attn_h16_kernel, cudaFuncAttributeMaxDynamicSharedMemorySize, ATT_SMEM);
    attn_h16_kernel<<<dim3(TT / 128, 16, 2), 256, ATT_SMEM>>>(qkv16, y16);

    // 3) output projection (fp16): -> fp32 out
    h16_gemm_bias<<<dim3(1024 / 128, 4096 / 128), 256, GEMM_SMEM>>>(
        y16, wtp, b_proj, out, cosb, sinb, 4096, 1024, 1024, 0);
}

// round 17
// speedup vs baseline: 2.7090x; 1.1572x over previous
#include <cuda_runtime.h>
#include <cuda_fp16.h>
#include <cstdint>

// Problem constants: B=2, T=2048, C=1024, H=16, D=64
#define TT 2048

// Scratch (allocation-free rule: __device__ globals)
__device__ __half g_x16[2 * 2048 * 1024];        // x fp16
__device__ __half g_qkv16[2 * 2048 * 3 * 1024];  // [B,T,3,H,D] fp16 (q,k normed+roped)
__device__ __half g_y16[2 * 2048 * 1024];        // [B,T,H,D] fp16
__device__ __half g_wta16[3072 * 1024];          // W_attn^T fp16 [N][K]
__device__ __half g_wtp16[1024 * 1024];          // W_proj^T fp16 [N][K]

__device__ __forceinline__ uint32_t f2h2(float lo, float hi) {
    __half2 h = __floats2half2_rn(lo, hi);
    return *reinterpret_cast<uint32_t*>(&h);
}

__device__ __forceinline__ void mma_f16(float* c, const uint32_t* a, const uint32_t* b) {
    asm volatile(
        "mma.sync.aligned.m16n8k16.row.col.f32.f16.f16.f32 "
        "{%0,%1,%2,%3}, {%4,%5,%6,%7}, {%8,%9}, {%0,%1,%2,%3};\n"
        : "+f"(c[0]), "+f"(c[1]), "+f"(c[2]), "+f"(c[3])
        : "r"(a[0]), "r"(a[1]), "r"(a[2]), "r"(a[3]), "r"(b[0]), "r"(b[1]));
}

#define LDSM_X4(r, addr) \
    asm volatile("ldmatrix.sync.aligned.m8n8.x4.shared.b16 {%0,%1,%2,%3}, [%4];" \
        : "=r"((r)[0]), "=r"((r)[1]), "=r"((r)[2]), "=r"((r)[3]) : "r"(addr))
#define LDSM_X4T(r, addr) \
    asm volatile("ldmatrix.sync.aligned.m8n8.x4.trans.shared.b16 {%0,%1,%2,%3}, [%4];" \
        : "=r"((r)[0]), "=r"((r)[1]), "=r"((r)[2]), "=r"((r)[3]) : "r"(addr))

#define CP_ASYNC16(dst_u32, src) \
    asm volatile("cp.async.cg.shared.global [%0], [%1], 16;\n" :: "r"(dst_u32), "l"(src))
#define CP_COMMIT() asm volatile("cp.async.commit_group;\n" ::: "memory")
#define CP_WAIT2()  asm volatile("cp.async.wait_group 2;\n" ::: "memory")

// ---------------------------------------------------------------------------
// Merged prepass: blocks [0,4096) convert x; [4096,7168) transpose W_attn;
// [7168,8192) transpose W_proj.
// ---------------------------------------------------------------------------
__global__ __launch_bounds__(256)
void prepass_kernel(const float* __restrict__ x, __half* __restrict__ x16,
                    const float* __restrict__ Wa, __half* __restrict__ wta,
                    const float* __restrict__ Wp, __half* __restrict__ wtp) {
    __shared__ float t[32][33];
    const int bid = blockIdx.x;
    if (bid < 4096) {
        const long i = ((long)bid * 256 + threadIdx.x) * 4;
        float4 v = *(const float4*)(x + i);
        uint2 u;
        u.x = f2h2(v.x, v.y);
        u.y = f2h2(v.z, v.w);
        *(uint2*)(x16 + i) = u;
        return;
    }
    const float* W;
    __half* Wt;
    int idx, K, N;
    if (bid < 7168) { idx = bid - 4096; W = Wa; Wt = wta; K = 1024; N = 3072; }
    else            { idx = bid - 7168; W = Wp; Wt = wtp; K = 1024; N = 1024; }
    const int nblk = N / 32;
    const int n0 = (idx % nblk) * 32, k0 = (idx / nblk) * 32;
    const int xx = threadIdx.x & 31, yy = threadIdx.x >> 5;
#pragma unroll
    for (int i = 0; i < 4; i++)
        t[yy + 8 * i][xx] = W[(long)(k0 + yy + 8 * i) * N + n0 + xx];
    __syncthreads();
#pragma unroll
    for (int i = 0; i < 4; i++)
        Wt[(long)(n0 + yy + 8 * i) * K + k0 + xx] = __float2half_rn(t[xx][yy + 8 * i]);
}

// ---------------------------------------------------------------------------
// FP16 GEMM with bias, cp.async 4-stage pipeline, ldmatrix fragments.
// mode 0: fp32 out. mode 1: fp16 out + fused RMSNorm+RoPE on q/k tiles.
// 256 thr, 8 warps (4x2), 128x128 tile, BK=32. Row pitch 80 B (AP=20 words).
// ---------------------------------------------------------------------------
#define AP 20
#define GST 2560
#define GEMM_SMEM (8 * GST * 4)

__global__ __launch_bounds__(256, 2)
void h16_gemm_bias(const __half* __restrict__ A, const __half* __restrict__ Bt,
                   const float* __restrict__ bias, void* __restrict__ CoutV,
                   const float* __restrict__ cosb, const float* __restrict__ sinb,
                   int M, int N, int K, int mode) {
    extern __shared__ uint32_t gsm[];
    const uint32_t smb = (uint32_t)__cvta_generic_to_shared(gsm);

    const int tid = threadIdx.x;
    const int lane = tid & 31;
    const int warp = tid >> 5;
    const int gid = lane >> 2;
    const int tig = lane & 3;
    const int wm = warp >> 1;
    const int wn = warp & 1;
    const int m0w = wm * 32;
    const int n0w = wn * 64;
    const int br = blockIdx.y * 128;
    const int bc = blockIdx.x * 128;

    // ldmatrix per-lane offsets (bytes)
    const uint32_t aoff = (uint32_t)((lane & 15) * 80 + (lane >> 4) * 16);
    const uint32_t boff = (uint32_t)(((lane & 7) + ((lane >> 4) & 1) * 8) * 80
                                     + ((lane >> 3) & 1) * 16);

    const int r0c = tid >> 2, o0c = tid & 3;
    const int r1c = (tid + 256) >> 2, o1c = tid & 3;
    const uint32_t ad0 = (uint32_t)(r0c * 80 + o0c * 16);
    const uint32_t ad1 = (uint32_t)(r1c * 80 + o1c * 16);

    const __half* A0 = A + (long)(br + r0c) * K + o0c * 8;
    const __half* A1 = A + (long)(br + r1c) * K + o1c * 8;
    const __half* B0 = Bt + (long)(bc + r0c) * K + o0c * 8;
    const __half* B1 = Bt + (long)(bc + r1c) * K + o1c * 8;

    float c[2][8][4];
#pragma unroll
    for (int mi = 0; mi < 2; mi++)
#pragma unroll
        for (int nj = 0; nj < 8; nj++)
#pragma unroll
            for (int e = 0; e < 4; e++) c[mi][nj][e] = 0.f;

    const int nch = K >> 5;
#pragma unroll
    for (int p = 0; p < 3; p++) {
        const uint32_t as_s = smb + (uint32_t)(p * GST * 4);
        const uint32_t bs_s = smb + (uint32_t)((4 + p) * GST * 4);
        CP_ASYNC16(as_s + ad0, A0 + p * 32);
        CP_ASYNC16(as_s + ad1, A1 + p * 32);
        CP_ASYNC16(bs_s + ad0, B0 + p * 32);
        CP_ASYNC16(bs_s + ad1, B1 + p * 32);
        CP_COMMIT();
    }

    for (int ch = 0; ch < nch; ch++) {
        CP_WAIT2();
        __syncthreads();

        const int ci = ch + 3;
        if (ci < nch) {
            const uint32_t as_s = smb + (uint32_t)((ci & 3) * GST * 4);
            const uint32_t bs_s = smb + (uint32_t)((4 + (ci & 3)) * GST * 4);
            CP_ASYNC16(as_s + ad0, A0 + ci * 32);
            CP_ASYNC16(as_s + ad1, A1 + ci * 32);
            CP_ASYNC16(bs_s + ad0, B0 + ci * 32);
            CP_ASYNC16(bs_s + ad1, B1 + ci * 32);
        }
        CP_COMMIT();

        const uint32_t abase = smb + (uint32_t)((ch & 3) * GST * 4)
                             + (uint32_t)(m0w * 80) + aoff;
        const uint32_t bbase = smb + (uint32_t)((4 + (ch & 3)) * GST * 4)
                             + (uint32_t)(n0w * 80) + boff;
#pragma unroll
        for (int ks = 0; ks < 2; ks++) {
            uint32_t a[2][4];
            LDSM_X4(a[0], abase + ks * 32);
            LDSM_X4(a[1], abase + 1280 + ks * 32);   // +16 rows * 80B
#pragma unroll
            for (int njp = 0; njp < 4; njp++) {
                uint32_t b4[4];
                LDSM_X4(b4, bbase + njp * 1280 + ks * 32);
                mma_f16(c[0][2 * njp],     a[0], &b4[0]);
                mma_f16(c[1][2 * njp],     a[1], &b4[0]);
                mma_f16(c[0][2 * njp + 1], a[0], &b4[2]);
                mma_f16(c[1][2 * njp + 1], a[1], &b4[2]);
            }
        }
    }

    // ---- epilogue ----
    if (mode == 1) {
        __half* Ch = (__half*)CoutV;
        const bool donr = (bc < 2048);   // q/k tiles get RMSNorm+RoPE
#pragma unroll
        for (int mi = 0; mi < 2; mi++) {
#pragma unroll
            for (int hf = 0; hf < 2; hf++) {
                const int row = br + m0w + mi * 16 + gid + hf * 8;
                float o[8][2];
#pragma unroll
                for (int nj = 0; nj < 8; nj++) {
                    int col = bc + n0w + nj * 8 + tig * 2;
                    float2 bb = *(const float2*)(bias + col);
                    o[nj][0] = c[mi][nj][2 * hf + 0] + bb.x;
                    o[nj][1] = c[mi][nj][2 * hf + 1] + bb.y;
                }
                if (donr) {
                    float ssum = 0.f;
#pragma unroll
                    for (int nj = 0; nj < 8; nj++)
                        ssum += o[nj][0] * o[nj][0] + o[nj][1] * o[nj][1];
                    ssum += __shfl_xor_sync(0xffffffffu, ssum, 1);
                    ssum += __shfl_xor_sync(0xffffffffu, ssum, 2);
                    const float rn = rsqrtf(ssum * (1.f / 64.f) + 1.1920929e-07f);
                    float nv[8][2];
#pragma unroll
                    for (int nj = 0; nj < 8; nj++) {
                        nv[nj][0] = o[nj][0] * rn;
                        nv[nj][1] = o[nj][1] * rn;
                    }
                    const int t = row & (TT - 1);
#pragma unroll
                    for (int nj = 0; nj < 8; nj++) {
                        int d = nj * 8 + tig * 2;
                        float2 cv = *(const float2*)(cosb + t * 64 + d);
                        float2 sv = *(const float2*)(sinb + t * 64 + d);
                        float rr0 = (nj < 4) ? -nv[nj + 4][0] : nv[nj - 4][0];
                        float rr1 = (nj < 4) ? -nv[nj + 4][1] : nv[nj - 4][1];
                        o[nj][0] = nv[nj][0] * cv.x + rr0 * sv.x;
                        o[nj][1] = nv[nj][1] * cv.y + rr1 * sv.y;
                    }
                }
#pragma unroll
                for (int nj = 0; nj < 8; nj++) {
                    int col = bc + n0w + nj * 8 + tig * 2;
                    *(uint32_t*)(Ch + (long)row * N + col) = f2h2(o[nj][0], o[nj][1]);
                }
            }
        }
    } else {
        float* Cf = (float*)CoutV;
#pragma unroll
        for (int mi = 0; mi < 2; mi++) {
            int row = br + m0w + mi * 16 + gid;
#pragma unroll
            for (int nj = 0; nj < 8; nj++) {
                int col = bc + n0w + nj * 8 + tig * 2;
                float2 bb = *(const float2*)(bias + col);
                *(float2*)(Cf + (long)row * N + col) =
                    make_float2(c[mi][nj][0] + bb.x, c[mi][nj][1] + bb.y);
                *(float2*)(Cf + (long)(row + 8) * N + col) =
                    make_float2(c[mi][nj][2] + bb.x, c[mi][nj][3] + bb.y);
            }
        }
    }
}

// ---------------------------------------------------------------------------
// FP16 flash attention: fixed-max softmax, 4-stage cp.async K/V,
// register-resident P, ldmatrix K/V fragments.
// ---------------------------------------------------------------------------
#define TPW 36
#define AST 2304
#define ATT_SMEM ((8 * AST + 4608) * 4)

__global__ __launch_bounds__(256, 2)
void attn_h16_kernel(const __half* __restrict__ qkv, __half* __restrict__ y) {
    extern __shared__ uint32_t smu[];
    uint32_t* Ps = smu + 8 * AST;
    const uint32_t smb = (uint32_t)__cvta_generic_to_shared(smu);
    const uint32_t vs_b0 = smb + 4 * AST * 4;

    const int qb = (int)(gridDim.x - 1) - (int)blockIdx.x;
    const int h = blockIdx.y, b = blockIdx.z;
    const int tid = threadIdx.x;
    const int lane = tid & 31, warp = tid >> 5;
    const int gid = lane >> 2, tig = lane & 3;
    const int r0 = warp * 16;

    // ldmatrix per-lane offsets (bytes), pitch 144
    const uint32_t koff = (uint32_t)(((lane & 7) + ((lane >> 4) & 1) * 8) * 144
                                     + ((lane >> 3) & 1) * 16);

    const int kc0 = tid * 2, kc1 = tid * 2 + 1;
    const int krow0 = kc0 >> 3, ko0 = kc0 & 7;
    const int krow1 = kc1 >> 3, ko1 = kc1 & 7;
    const long kvb0 = ((long)(b * TT + krow0) * 3) * 1024 + h * 64 + ko0 * 8;
    const long kvb1 = ((long)(b * TT + krow1) * 3) * 1024 + h * 64 + ko1 * 8;
    const uint32_t kd0 = (uint32_t)(krow0 * 144 + ko0 * 16);
    const uint32_t kd1 = (uint32_t)(krow1 * 144 + ko1 * 16);

    const int nkv = 2 * (qb + 1);

#pragma unroll
    for (int p = 0; p < 3; p++) {
        if (p < nkv) {
            const uint32_t ko = (uint32_t)(p * AST * 4);
            const __half* s0 = qkv + kvb0 + (long)p * 64 * 3072 + 1024;
            const __half* s1 = qkv + kvb1 + (long)p * 64 * 3072 + 1024;
            CP_ASYNC16(smb + ko + kd0, s0);
            CP_ASYNC16(smb + ko + kd1, s1);
            CP_ASYNC16(vs_b0 + ko + kd0, s0 + 1024);
            CP_ASYNC16(vs_b0 + ko + kd1, s1 + 1024);
        }
        CP_COMMIT();
    }

    {
        const __half2 qscale = __floats2half2_rn(0.125f, 0.125f);
        const int row = tid >> 1;
        const int dh = (tid & 1) * 32;
        const uint4* src = (const uint4*)(qkv + ((long)(b * TT + qb * 128 + row) * 3) * 1024 + h * 64 + dh);
#pragma unroll
        for (int j = 0; j < 4; j++) {
            uint4 u = src[j];
            __half2* hp = (__half2*)&u;
            hp[0] = __hmul2(hp[0], qscale);
            hp[1] = __hmul2(hp[1], qscale);
            hp[2] = __hmul2(hp[2], qscale);
            hp[3] = __hmul2(hp[3], qscale);
            *(uint4*)&Ps[row * TPW + (tid & 1) * 16 + j * 4] = u;
        }
    }
    __syncthreads();
    uint32_t qa[4][4];
#pragma unroll
    for (int ks = 0; ks < 4; ks++) {
        int base = (r0 + gid) * TPW + ks * 8 + tig;
        qa[ks][0] = Ps[base];
        qa[ks][1] = Ps[base + 8 * TPW];
        qa[ks][2] = Ps[base + 4];
        qa[ks][3] = Ps[base + 8 * TPW + 4];
    }

    float cO[8][4];
#pragma unroll
    for (int nj = 0; nj < 8; nj++)
#pragma unroll
        for (int e = 0; e < 4; e++) cO[nj][e] = 0.f;
    float lp0 = 0.f, lp1 = 0.f;

    for (int kb = 0; kb < nkv; kb++) {
        CP_WAIT2();
        __syncthreads();

        const int ti = kb + 3;
        if (ti < nkv) {
            const uint32_t ko = (uint32_t)((ti & 3) * AST * 4);
            const __half* s0 = qkv + kvb0 + (long)ti * 64 * 3072 + 1024;
            const __half* s1 = qkv + kvb1 + (long)ti * 64 * 3072 + 1024;
            CP_ASYNC16(smb + ko + kd0, s0);
            CP_ASYNC16(smb + ko + kd1, s1);
            CP_ASYNC16(vs_b0 + ko + kd0, s0 + 1024);
            CP_ASYNC16(vs_b0 + ko + kd1, s1 + 1024);
        }
        CP_COMMIT();

        const uint32_t kcb = smb + (uint32_t)((kb & 3) * AST * 4) + koff;
        const uint32_t vrb = vs_b0 + (uint32_t)((kb & 3) * AST * 4);

        // ---- S = Q @ K^T (ldmatrix.x4 nj-pairs) ----
        float cS[8][4];
#pragma unroll
        for (int nj = 0; nj < 8; nj++)
#pragma unroll
            for (int e = 0; e < 4; e++) cS[nj][e] = 0.f;

#pragma unroll
        for (int ks = 0; ks < 4; ks++) {
#pragma unroll
            for (int njp = 0; njp < 4; njp++) {
                uint32_t k4[4];
                LDSM_X4(k4, kcb + njp * 2304 + ks * 32);  // 16 rows * 144B
                mma_f16(cS[2 * njp],     qa[ks], &k4[0]);
                mma_f16(cS[2 * njp + 1], qa[ks], &k4[2]);
            }
        }

        if (kb >= 2 * qb) {  // causal diagonal tiles
            int rA = qb * 128 + r0 + gid;
            int rB = rA + 8;
#pragma unroll
            for (int nj = 0; nj < 8; nj++) {
                int col = kb * 64 + nj * 8 + 2 * tig;
                if (col     > rA) cS[nj][0] = -3.0e38f;
                if (col + 1 > rA) cS[nj][1] = -3.0e38f;
                if (col     > rB) cS[nj][2] = -3.0e38f;
                if (col + 1 > rB) cS[nj][3] = -3.0e38f;
            }
        }

        // ---- fixed-max softmax: p = exp(s - 8) ----
#pragma unroll
        for (int nj = 0; nj < 8; nj++) {
            cS[nj][0] = __expf(cS[nj][0] - 8.0f); lp0 += cS[nj][0];
            cS[nj][1] = __expf(cS[nj][1] - 8.0f); lp0 += cS[nj][1];
            cS[nj][2] = __expf(cS[nj][2] - 8.0f); lp1 += cS[nj][2];
            cS[nj][3] = __expf(cS[nj][3] - 8.0f); lp1 += cS[nj][3];
        }

        // ---- pack P: S C-frags -> PV A-frags (registers only) ----
        uint32_t pf[4][4];
#pragma unroll
        for (int ks = 0; ks < 4; ks++) {
            pf[ks][0] = f2h2(cS[2 * ks][0],     cS[2 * ks][1]);
            pf[ks][1] = f2h2(cS[2 * ks][2],     cS[2 * ks][3]);
            pf[ks][2] = f2h2(cS[2 * ks + 1][0], cS[2 * ks + 1][1]);
            pf[ks][3] = f2h2(cS[2 * ks + 1][2], cS[2 * ks + 1][3]);
        }

        // ---- O += P @ V (ldmatrix.x4.trans nj-pairs) ----
#pragma unroll
        for (int ks = 0; ks < 4; ks++) {
            const uint32_t vrow = vrb + (uint32_t)((ks * 16 + (lane & 15)) * 144
                                                   + ((lane >> 4) & 1) * 16);
#pragma unroll
            for (int njp = 0; njp < 4; njp++) {
                uint32_t v4[4];
                LDSM_X4T(v4, vrow + njp * 32);
                mma_f16(cO[2 * njp],     pf[ks], &v4[0]);
                mma_f16(cO[2 * njp + 1], pf[ks], &v4[2]);
            }
        }
    }

    lp0 += __shfl_xor_sync(0xffffffffu, lp0, 1);
    lp0 += __shfl_xor_sync(0xffffffffu, lp0, 2);
    lp1 += __shfl_xor_sync(0xffffffffu, lp1, 1);
    lp1 += __shfl_xor_sync(0xffffffffu, lp1, 2);
    float inv0 = 1.0f / lp0, inv1 = 1.0f / lp1;
    long rowA = (long)(b * TT + qb * 128 + r0 + gid) * 1024 + h * 64;
    long rowB = rowA + 8 * 1024;
#pragma unroll
    for (int nj = 0; nj < 8; nj++) {
        int col = nj * 8 + 2 * tig;
        *(uint32_t*)(y + rowA + col) = f2h2(cO[nj][0] * inv0, cO[nj][1] * inv0);
        *(uint32_t*)(y + rowB + col) = f2h2(cO[nj][2] * inv1, cO[nj][3] * inv1);
    }
}

// ---------------------------------------------------------------------------
extern "C" void kernel_launch(void* const* d_in, const int* in_sizes, int n_in,
                              void* d_out, int out_size) {
    const float* x      = (const float*)d_in[0];
    const float* cosb   = (const float*)d_in[1];
    const float* sinb   = (const float*)d_in[2];
    const float* W_attn = (const float*)d_in[3];
    const float* b_attn = (const float*)d_in[4];
    const float* W_proj = (const float*)d_in[5];
    const float* b_proj = (const float*)d_in[6];
    float* out = (float*)d_out;

    __half *x16, *qkv16, *y16, *wta, *wtp;
    cudaGetSymbolAddress((void**)&x16, g_x16);
    cudaGetSymbolAddress((void**)&qkv16, g_qkv16);
    cudaGetSymbolAddress((void**)&y16, g_y16);
    cudaGetSymbolAddress((void**)&wta, g_wta16);
    cudaGetSymbolAddress((void**)&wtp, g_wtp16);

    // 0) merged prepass: x->fp16, both weight transposes
    prepass_kernel<<<8192, 256>>>(x, x16, W_attn, wta, W_proj, wtp);

    // 1) QKV GEMM with fused RMSNorm+RoPE epilogue: -> g_qkv16
    cudaFuncSetAttribute(h16_gemm_bias, cudaFuncAttributeMaxDynamicSharedMemorySize, GEMM_SMEM);
    h16_gemm_bias<<<dim3(3072 / 128, 4096 / 128), 256, GEMM_SMEM>>>(
        x16, wta, b_attn, qkv16, cosb, sinb, 4096, 3072, 1024, 1);

    // 2) causal flash attention (fp16, register-resident P, ldmatrix frags)
    cudaFuncSetAttribute(attn_h16_kernel, cudaFuncAttributeMaxDynamicSharedMemorySize, ATT_SMEM);
    attn_h16_kernel<<<dim3(TT / 128, 16, 2), 256, ATT_SMEM>>>(qkv16, y16);

    // 3) output projection (fp16): -> fp32 out
    h16_gemm_bias<<<dim3(1024 / 128, 4096 / 128), 256, GEMM_SMEM>>>(
        y16, wtp, b_proj, out, cosb, sinb, 4096, 1024, 1024, 0);
}